// round 1
// baseline (speedup 1.0000x reference)
#include <cuda_runtime.h>
#include <math.h>

#define BATCH 2
#define SLEN 4096
#define DMODEL 128
#define NHEAD 4
#define HDIM 32
#define NROW (BATCH*SLEN)   // 8192
#define NHB  (BATCH*NHEAD)  // 8

// Scratch (device globals — no allocation allowed)
__device__ float g_pe[SLEN*DMODEL];
__device__ float g_q[BATCH*SLEN*DMODEL];
__device__ float g_k[BATCH*SLEN*DMODEL];
__device__ float g_v[BATCH*SLEN*DMODEL];
__device__ float g_o[BATCH*SLEN*DMODEL];

// ---------------------------------------------------------------------------
// Positional encoding: pe[s,2i] = sin(s / 10000^(2i/128)), pe[s,2i+1] = cos(.)
// Replicate jax fp32 angle arithmetic, then take high-precision sin/cos of the
// fp32-rounded angle (double sin handles the large-argument range reduction).
// ---------------------------------------------------------------------------
__global__ void pe_kernel() {
    int idx = blockIdx.x * blockDim.x + threadIdx.x;
    if (idx >= SLEN * (DMODEL/2)) return;
    int s = idx / (DMODEL/2);
    int i = idx % (DMODEL/2);
    float e = (2.0f * (float)i) / (float)DMODEL;          // exact in fp32
    double divd = pow(10000.0, (double)e);
    float fdiv = (float)divd;
    float a = (float)s / fdiv;                            // fp32 like jax
    double ad = (double)a;
    g_pe[s*DMODEL + 2*i]     = (float)sin(ad);
    g_pe[s*DMODEL + 2*i + 1] = (float)cos(ad);
}

// ---------------------------------------------------------------------------
// QKV projection: x = emb[tok] + pe;  q/k/v = x @ W^T   (W is [out,in])
// Block: 64 rows. smem: Xs[64][132] row-major, Ws (transposed, k-major) [128][20]
// Thread (ty=tid/16, tx=tid%16): 4 rows x 1 col micro-tile, 16-col chunks.
// ---------------------------------------------------------------------------
__global__ __launch_bounds__(256) void qkv_kernel(
        const int* __restrict__ seq, const float* __restrict__ emb,
        const float* __restrict__ wq, const float* __restrict__ wk,
        const float* __restrict__ wv) {
    __shared__ float Xs[64][132];
    __shared__ float Ws[128][20];
    int tid = threadIdx.x;
    int r0 = blockIdx.x * 64;

    // Load X tile: 64 rows x 32 float4 (coalesced along d)
    #pragma unroll
    for (int it = 0; it < 8; it++) {
        int idx = tid + it * 256;
        int rl = idx >> 5, d4 = idx & 31;
        int row = r0 + rl;
        int tok = seq[row];
        int sp = row & (SLEN - 1);
        float4 e4 = *(const float4*)(emb + (long)tok * DMODEL + 4*d4);
        float4 p4 = *(const float4*)(g_pe + sp * DMODEL + 4*d4);
        float4 x;
        x.x = e4.x + p4.x; x.y = e4.y + p4.y;
        x.z = e4.z + p4.z; x.w = e4.w + p4.w;
        *(float4*)&Xs[rl][4*d4] = x;
    }

    int ty = tid >> 4, tx = tid & 15;
    for (int w = 0; w < 3; w++) {
        const float* W = (w == 0) ? wq : ((w == 1) ? wk : wv);
        float* out = (w == 0) ? g_q : ((w == 1) ? g_k : g_v);
        for (int ch = 0; ch < 8; ch++) {
            int c0 = ch * 16;
            __syncthreads();
            // Load 16 cols x 128 k of W, stored k-major: Ws[k][col]
            #pragma unroll
            for (int it = 0; it < 2; it++) {
                int idx = tid + it * 256;
                int e  = idx & 15;   // col
                int k4 = idx >> 4;   // 0..31
                float4 w4 = *(const float4*)(W + (c0 + e) * DMODEL + 4*k4);
                Ws[4*k4+0][e] = w4.x; Ws[4*k4+1][e] = w4.y;
                Ws[4*k4+2][e] = w4.z; Ws[4*k4+3][e] = w4.w;
            }
            __syncthreads();
            float acc0 = 0.f, acc1 = 0.f, acc2 = 0.f, acc3 = 0.f;
            #pragma unroll 16
            for (int k = 0; k < DMODEL; k++) {
                float wval = Ws[k][tx];
                acc0 += Xs[4*ty+0][k] * wval;
                acc1 += Xs[4*ty+1][k] * wval;
                acc2 += Xs[4*ty+2][k] * wval;
                acc3 += Xs[4*ty+3][k] * wval;
            }
            out[(r0 + 4*ty + 0) * DMODEL + c0 + tx] = acc0;
            out[(r0 + 4*ty + 1) * DMODEL + c0 + tx] = acc1;
            out[(r0 + 4*ty + 2) * DMODEL + c0 + tx] = acc2;
            out[(r0 + 4*ty + 3) * DMODEL + c0 + tx] = acc3;
        }
    }
}

// ---------------------------------------------------------------------------
// Flash attention (fp32, causal, abs() scores). Head hb = b*4 + h is the
// contiguous [4096,32] slice at offset hb*SLEN*HDIM of the [B,S,128] buffers.
// Block = one 64-row Q tile of one head. 256 threads:
//   ty=tid/16 owns rows 4ty..4ty+3 (all phases), tx=tid%16.
//   S-phase micro: 4x4 (cols 4tx), PV-phase micro: 4x2 (cols 2tx).
// ---------------------------------------------------------------------------
__global__ __launch_bounds__(256) void attn_kernel() {
    int qt = (int)(gridDim.x - 1) - (int)blockIdx.x;  // heavy tiles first
    int hb = blockIdx.y;
    const float* Qb = g_q + (long)hb * SLEN * HDIM;
    const float* Kb = g_k + (long)hb * SLEN * HDIM;
    const float* Vb = g_v + (long)hb * SLEN * HDIM;
    float* Ob = g_o + (long)hb * SLEN * HDIM;

    __shared__ float Qs[32][68];   // k-major (transposed), padded
    __shared__ float Ks[32][68];
    __shared__ float Vs[64][32];
    __shared__ float Ps[64][64];

    int tid = threadIdx.x;
    int ty = tid >> 4, tx = tid & 15;

    const float scale = 0.17677669529663687f;  // 1/sqrt(32)

    // Load Q tile (scaled), transposed into Qs[d][row]
    #pragma unroll
    for (int it = 0; it < 2; it++) {
        int idx = tid + it * 256;          // 512 float4
        int rl = idx >> 3, d4 = idx & 7;
        float4 q4 = *(const float4*)(Qb + (qt*64 + rl) * HDIM + 4*d4);
        Qs[4*d4+0][rl] = q4.x * scale;
        Qs[4*d4+1][rl] = q4.y * scale;
        Qs[4*d4+2][rl] = q4.z * scale;
        Qs[4*d4+3][rl] = q4.w * scale;
    }

    float m[4], l[4], o[4][2];
    #pragma unroll
    for (int i = 0; i < 4; i++) {
        m[i] = 0.f; l[i] = 0.f; o[i][0] = 0.f; o[i][1] = 0.f;
    }

    for (int jt = 0; jt <= qt; jt++) {
        __syncthreads();  // previous PV done with Vs/Ps before reload
        // Load K (transposed) and V (natural)
        #pragma unroll
        for (int it = 0; it < 2; it++) {
            int idx = tid + it * 256;
            int rl = idx >> 3, d4 = idx & 7;
            float4 k4 = *(const float4*)(Kb + (jt*64 + rl) * HDIM + 4*d4);
            Ks[4*d4+0][rl] = k4.x; Ks[4*d4+1][rl] = k4.y;
            Ks[4*d4+2][rl] = k4.z; Ks[4*d4+3][rl] = k4.w;
            float4 v4 = *(const float4*)(Vb + (jt*64 + rl) * HDIM + 4*d4);
            *(float4*)&Vs[rl][4*d4] = v4;
        }
        __syncthreads();

        // S = Q @ K^T (scaled)
        float s[4][4];
        #pragma unroll
        for (int i = 0; i < 4; i++)
            #pragma unroll
            for (int j = 0; j < 4; j++) s[i][j] = 0.f;
        #pragma unroll
        for (int k = 0; k < 32; k++) {
            float4 a = *(const float4*)&Qs[k][4*ty];
            float4 b = *(const float4*)&Ks[k][4*tx];
            s[0][0] += a.x*b.x; s[0][1] += a.x*b.y; s[0][2] += a.x*b.z; s[0][3] += a.x*b.w;
            s[1][0] += a.y*b.x; s[1][1] += a.y*b.y; s[1][2] += a.y*b.z; s[1][3] += a.y*b.w;
            s[2][0] += a.z*b.x; s[2][1] += a.z*b.y; s[2][2] += a.z*b.z; s[2][3] += a.z*b.w;
            s[3][0] += a.w*b.x; s[3][1] += a.w*b.y; s[3][2] += a.w*b.z; s[3][3] += a.w*b.w;
        }

        // abs + causal mask (only diagonal tile needs masking)
        if (jt == qt) {
            int gq = 4*ty;      // within-tile row
            int gk = 4*tx;      // within-tile col
            #pragma unroll
            for (int i = 0; i < 4; i++)
                #pragma unroll
                for (int j = 0; j < 4; j++) {
                    float v = fabsf(s[i][j]);
                    s[i][j] = (gk + j > gq + i) ? -INFINITY : v;
                }
        } else {
            #pragma unroll
            for (int i = 0; i < 4; i++)
                #pragma unroll
                for (int j = 0; j < 4; j++) s[i][j] = fabsf(s[i][j]);
        }

        // Online softmax: row max (reduce across tx = lane%16 group)
        float mx[4], alpha[4];
        #pragma unroll
        for (int i = 0; i < 4; i++) {
            mx[i] = fmaxf(fmaxf(s[i][0], s[i][1]), fmaxf(s[i][2], s[i][3]));
            #pragma unroll
            for (int off = 1; off < 16; off <<= 1)
                mx[i] = fmaxf(mx[i], __shfl_xor_sync(0xffffffffu, mx[i], off));
            float mn = fmaxf(m[i], mx[i]);
            alpha[i] = __expf(m[i] - mn);
            m[i] = mn;
        }

        float rs[4];
        #pragma unroll
        for (int i = 0; i < 4; i++) {
            float r = 0.f;
            #pragma unroll
            for (int j = 0; j < 4; j++) {
                float p = __expf(s[i][j] - m[i]);  // masked -> exp(-inf)=0
                s[i][j] = p;
                r += p;
            }
            #pragma unroll
            for (int off = 1; off < 16; off <<= 1)
                r += __shfl_xor_sync(0xffffffffu, r, off);
            rs[i] = r;
            l[i] = l[i] * alpha[i] + rs[i];
        }

        // store P (row-major, STS.128 conflict-free)
        #pragma unroll
        for (int i = 0; i < 4; i++)
            *(float4*)&Ps[4*ty+i][4*tx] = make_float4(s[i][0], s[i][1], s[i][2], s[i][3]);
        __syncthreads();

        // O = O*alpha + P @ V
        #pragma unroll
        for (int i = 0; i < 4; i++) { o[i][0] *= alpha[i]; o[i][1] *= alpha[i]; }
        #pragma unroll 16
        for (int k = 0; k < 64; k++) {
            float2 vv = *(const float2*)&Vs[k][2*tx];
            #pragma unroll
            for (int i = 0; i < 4; i++) {
                float p = Ps[4*ty+i][k];   // broadcast read, conflict-free
                o[i][0] += p * vv.x;
                o[i][1] += p * vv.y;
            }
        }
    }

    // normalize + store
    #pragma unroll
    for (int i = 0; i < 4; i++) {
        float inv = 1.0f / l[i];
        float2 r;
        r.x = o[i][0] * inv;
        r.y = o[i][1] * inv;
        *(float2*)(Ob + (qt*64 + 4*ty + i) * HDIM + 2*tx) = r;
    }
}

// ---------------------------------------------------------------------------
// Output projection: out = O @ wo^T  (same structure as qkv, single W)
// ---------------------------------------------------------------------------
__global__ __launch_bounds__(256) void oproj_kernel(
        const float* __restrict__ wo, float* __restrict__ out) {
    __shared__ float Xs[64][132];
    __shared__ float Ws[128][20];
    int tid = threadIdx.x;
    int r0 = blockIdx.x * 64;

    #pragma unroll
    for (int it = 0; it < 8; it++) {
        int idx = tid + it * 256;
        int rl = idx >> 5, d4 = idx & 31;
        float4 x = *(const float4*)(g_o + (long)(r0 + rl) * DMODEL + 4*d4);
        *(float4*)&Xs[rl][4*d4] = x;
    }

    int ty = tid >> 4, tx = tid & 15;
    for (int ch = 0; ch < 8; ch++) {
        int c0 = ch * 16;
        __syncthreads();
        #pragma unroll
        for (int it = 0; it < 2; it++) {
            int idx = tid + it * 256;
            int e  = idx & 15;
            int k4 = idx >> 4;
            float4 w4 = *(const float4*)(wo + (c0 + e) * DMODEL + 4*k4);
            Ws[4*k4+0][e] = w4.x; Ws[4*k4+1][e] = w4.y;
            Ws[4*k4+2][e] = w4.z; Ws[4*k4+3][e] = w4.w;
        }
        __syncthreads();
        float acc0 = 0.f, acc1 = 0.f, acc2 = 0.f, acc3 = 0.f;
        #pragma unroll 16
        for (int k = 0; k < DMODEL; k++) {
            float wval = Ws[k][tx];
            acc0 += Xs[4*ty+0][k] * wval;
            acc1 += Xs[4*ty+1][k] * wval;
            acc2 += Xs[4*ty+2][k] * wval;
            acc3 += Xs[4*ty+3][k] * wval;
        }
        out[(r0 + 4*ty + 0) * DMODEL + c0 + tx] = acc0;
        out[(r0 + 4*ty + 1) * DMODEL + c0 + tx] = acc1;
        out[(r0 + 4*ty + 2) * DMODEL + c0 + tx] = acc2;
        out[(r0 + 4*ty + 3) * DMODEL + c0 + tx] = acc3;
    }
}

extern "C" void kernel_launch(void* const* d_in, const int* in_sizes, int n_in,
                              void* d_out, int out_size) {
    const int*   seq = (const int*)d_in[0];
    const float* emb = (const float*)d_in[1];
    const float* wq  = (const float*)d_in[2];
    const float* wk  = (const float*)d_in[3];
    const float* wv  = (const float*)d_in[4];
    const float* wo  = (const float*)d_in[5];
    float* out = (float*)d_out;

    pe_kernel<<<(SLEN*(DMODEL/2) + 255)/256, 256>>>();
    qkv_kernel<<<NROW/64, 256>>>(seq, emb, wq, wk, wv);
    attn_kernel<<<dim3(SLEN/64, NHB), 256>>>();
    oproj_kernel<<<NROW/64, 256>>>(wo, out);
}

// round 2
// speedup vs baseline: 1.0006x; 1.0006x over previous
#include <cuda_runtime.h>
#include <math.h>

#define BATCH 2
#define SLEN 4096
#define DMODEL 128
#define NHEAD 4
#define HDIM 32
#define NROW (BATCH*SLEN)   // 8192
#define NHB  (BATCH*NHEAD)  // 8

// Scratch (device globals — no allocation allowed)
__device__ float g_pe[SLEN*DMODEL];
__device__ float g_q[BATCH*SLEN*DMODEL];
__device__ float g_k[BATCH*SLEN*DMODEL];
__device__ float g_v[BATCH*SLEN*DMODEL];
__device__ float g_o[BATCH*SLEN*DMODEL];

// ---------------------------------------------------------------------------
// Positional encoding: pe[s,2i] = sin(s / 10000^(2i/128)), pe[s,2i+1] = cos(.)
// Replicate jax fp32 angle arithmetic, then take high-precision sin/cos of the
// fp32-rounded angle (double sin handles the large-argument range reduction).
// ---------------------------------------------------------------------------
__global__ void pe_kernel() {
    int idx = blockIdx.x * blockDim.x + threadIdx.x;
    if (idx >= SLEN * (DMODEL/2)) return;
    int s = idx / (DMODEL/2);
    int i = idx % (DMODEL/2);
    float e = (2.0f * (float)i) / (float)DMODEL;          // exact in fp32
    double divd = pow(10000.0, (double)e);
    float fdiv = (float)divd;
    float a = (float)s / fdiv;                            // fp32 like jax
    double ad = (double)a;
    g_pe[s*DMODEL + 2*i]     = (float)sin(ad);
    g_pe[s*DMODEL + 2*i + 1] = (float)cos(ad);
}

// ---------------------------------------------------------------------------
// QKV projection: x = emb[tok] + pe;  q/k/v = x @ W^T   (W is [out,in])
// Block: 64 rows. smem: Xs[64][132] row-major, Ws (transposed, k-major) [128][20]
// Thread (ty=tid/16, tx=tid%16): 4 rows x 1 col micro-tile, 16-col chunks.
// ---------------------------------------------------------------------------
__global__ __launch_bounds__(256) void qkv_kernel(
        const int* __restrict__ seq, const float* __restrict__ emb,
        const float* __restrict__ wq, const float* __restrict__ wk,
        const float* __restrict__ wv) {
    __shared__ float Xs[64][132];
    __shared__ float Ws[128][20];
    int tid = threadIdx.x;
    int r0 = blockIdx.x * 64;

    // Load X tile: 64 rows x 32 float4 (coalesced along d)
    #pragma unroll
    for (int it = 0; it < 8; it++) {
        int idx = tid + it * 256;
        int rl = idx >> 5, d4 = idx & 31;
        int row = r0 + rl;
        int tok = seq[row];
        int sp = row & (SLEN - 1);
        float4 e4 = *(const float4*)(emb + (long)tok * DMODEL + 4*d4);
        float4 p4 = *(const float4*)(g_pe + sp * DMODEL + 4*d4);
        float4 x;
        x.x = e4.x + p4.x; x.y = e4.y + p4.y;
        x.z = e4.z + p4.z; x.w = e4.w + p4.w;
        *(float4*)&Xs[rl][4*d4] = x;
    }

    int ty = tid >> 4, tx = tid & 15;
    for (int w = 0; w < 3; w++) {
        const float* W = (w == 0) ? wq : ((w == 1) ? wk : wv);
        float* out = (w == 0) ? g_q : ((w == 1) ? g_k : g_v);
        for (int ch = 0; ch < 8; ch++) {
            int c0 = ch * 16;
            __syncthreads();
            // Load 16 cols x 128 k of W, stored k-major: Ws[k][col]
            #pragma unroll
            for (int it = 0; it < 2; it++) {
                int idx = tid + it * 256;
                int e  = idx & 15;   // col
                int k4 = idx >> 4;   // 0..31
                float4 w4 = *(const float4*)(W + (c0 + e) * DMODEL + 4*k4);
                Ws[4*k4+0][e] = w4.x; Ws[4*k4+1][e] = w4.y;
                Ws[4*k4+2][e] = w4.z; Ws[4*k4+3][e] = w4.w;
            }
            __syncthreads();
            float acc0 = 0.f, acc1 = 0.f, acc2 = 0.f, acc3 = 0.f;
            #pragma unroll 16
            for (int k = 0; k < DMODEL; k++) {
                float wval = Ws[k][tx];
                acc0 += Xs[4*ty+0][k] * wval;
                acc1 += Xs[4*ty+1][k] * wval;
                acc2 += Xs[4*ty+2][k] * wval;
                acc3 += Xs[4*ty+3][k] * wval;
            }
            out[(r0 + 4*ty + 0) * DMODEL + c0 + tx] = acc0;
            out[(r0 + 4*ty + 1) * DMODEL + c0 + tx] = acc1;
            out[(r0 + 4*ty + 2) * DMODEL + c0 + tx] = acc2;
            out[(r0 + 4*ty + 3) * DMODEL + c0 + tx] = acc3;
        }
    }
}

// ---------------------------------------------------------------------------
// Flash attention (fp32, causal, abs() scores). Head hb = b*4 + h is the
// contiguous [4096,32] slice at offset hb*SLEN*HDIM of the [B,S,128] buffers.
// Block = one 64-row Q tile of one head. 256 threads:
//   ty=tid/16 owns rows 4ty..4ty+3 (all phases), tx=tid%16.
//   S-phase micro: 4x4 (cols 4tx), PV-phase micro: 4x2 (cols 2tx).
// ---------------------------------------------------------------------------
__global__ __launch_bounds__(256) void attn_kernel() {
    int qt = (int)(gridDim.x - 1) - (int)blockIdx.x;  // heavy tiles first
    int hb = blockIdx.y;
    const float* Qb = g_q + (long)hb * SLEN * HDIM;
    const float* Kb = g_k + (long)hb * SLEN * HDIM;
    const float* Vb = g_v + (long)hb * SLEN * HDIM;
    float* Ob = g_o + (long)hb * SLEN * HDIM;

    __shared__ float Qs[32][68];   // k-major (transposed), padded
    __shared__ float Ks[32][68];
    __shared__ float Vs[64][32];
    __shared__ float Ps[64][64];

    int tid = threadIdx.x;
    int ty = tid >> 4, tx = tid & 15;

    const float scale = 0.17677669529663687f;  // 1/sqrt(32)

    // Load Q tile (scaled), transposed into Qs[d][row]
    #pragma unroll
    for (int it = 0; it < 2; it++) {
        int idx = tid + it * 256;          // 512 float4
        int rl = idx >> 3, d4 = idx & 7;
        float4 q4 = *(const float4*)(Qb + (qt*64 + rl) * HDIM + 4*d4);
        Qs[4*d4+0][rl] = q4.x * scale;
        Qs[4*d4+1][rl] = q4.y * scale;
        Qs[4*d4+2][rl] = q4.z * scale;
        Qs[4*d4+3][rl] = q4.w * scale;
    }

    float m[4], l[4], o[4][2];
    #pragma unroll
    for (int i = 0; i < 4; i++) {
        m[i] = 0.f; l[i] = 0.f; o[i][0] = 0.f; o[i][1] = 0.f;
    }

    for (int jt = 0; jt <= qt; jt++) {
        __syncthreads();  // previous PV done with Vs/Ps before reload
        // Load K (transposed) and V (natural)
        #pragma unroll
        for (int it = 0; it < 2; it++) {
            int idx = tid + it * 256;
            int rl = idx >> 3, d4 = idx & 7;
            float4 k4 = *(const float4*)(Kb + (jt*64 + rl) * HDIM + 4*d4);
            Ks[4*d4+0][rl] = k4.x; Ks[4*d4+1][rl] = k4.y;
            Ks[4*d4+2][rl] = k4.z; Ks[4*d4+3][rl] = k4.w;
            float4 v4 = *(const float4*)(Vb + (jt*64 + rl) * HDIM + 4*d4);
            *(float4*)&Vs[rl][4*d4] = v4;
        }
        __syncthreads();

        // S = Q @ K^T (scaled)
        float s[4][4];
        #pragma unroll
        for (int i = 0; i < 4; i++)
            #pragma unroll
            for (int j = 0; j < 4; j++) s[i][j] = 0.f;
        #pragma unroll
        for (int k = 0; k < 32; k++) {
            float4 a = *(const float4*)&Qs[k][4*ty];
            float4 b = *(const float4*)&Ks[k][4*tx];
            s[0][0] += a.x*b.x; s[0][1] += a.x*b.y; s[0][2] += a.x*b.z; s[0][3] += a.x*b.w;
            s[1][0] += a.y*b.x; s[1][1] += a.y*b.y; s[1][2] += a.y*b.z; s[1][3] += a.y*b.w;
            s[2][0] += a.z*b.x; s[2][1] += a.z*b.y; s[2][2] += a.z*b.z; s[2][3] += a.z*b.w;
            s[3][0] += a.w*b.x; s[3][1] += a.w*b.y; s[3][2] += a.w*b.z; s[3][3] += a.w*b.w;
        }

        // abs + causal mask (only diagonal tile needs masking)
        if (jt == qt) {
            int gq = 4*ty;      // within-tile row
            int gk = 4*tx;      // within-tile col
            #pragma unroll
            for (int i = 0; i < 4; i++)
                #pragma unroll
                for (int j = 0; j < 4; j++) {
                    float v = fabsf(s[i][j]);
                    s[i][j] = (gk + j > gq + i) ? -INFINITY : v;
                }
        } else {
            #pragma unroll
            for (int i = 0; i < 4; i++)
                #pragma unroll
                for (int j = 0; j < 4; j++) s[i][j] = fabsf(s[i][j]);
        }

        // Online softmax: row max (reduce across tx = lane%16 group)
        float mx[4], alpha[4];
        #pragma unroll
        for (int i = 0; i < 4; i++) {
            mx[i] = fmaxf(fmaxf(s[i][0], s[i][1]), fmaxf(s[i][2], s[i][3]));
            #pragma unroll
            for (int off = 1; off < 16; off <<= 1)
                mx[i] = fmaxf(mx[i], __shfl_xor_sync(0xffffffffu, mx[i], off));
            float mn = fmaxf(m[i], mx[i]);
            alpha[i] = __expf(m[i] - mn);
            m[i] = mn;
        }

        float rs[4];
        #pragma unroll
        for (int i = 0; i < 4; i++) {
            float r = 0.f;
            #pragma unroll
            for (int j = 0; j < 4; j++) {
                float p = __expf(s[i][j] - m[i]);  // masked -> exp(-inf)=0
                s[i][j] = p;
                r += p;
            }
            #pragma unroll
            for (int off = 1; off < 16; off <<= 1)
                r += __shfl_xor_sync(0xffffffffu, r, off);
            rs[i] = r;
            l[i] = l[i] * alpha[i] + rs[i];
        }

        // store P (row-major, STS.128 conflict-free)
        #pragma unroll
        for (int i = 0; i < 4; i++)
            *(float4*)&Ps[4*ty+i][4*tx] = make_float4(s[i][0], s[i][1], s[i][2], s[i][3]);
        __syncthreads();

        // O = O*alpha + P @ V
        #pragma unroll
        for (int i = 0; i < 4; i++) { o[i][0] *= alpha[i]; o[i][1] *= alpha[i]; }
        #pragma unroll 16
        for (int k = 0; k < 64; k++) {
            float2 vv = *(const float2*)&Vs[k][2*tx];
            #pragma unroll
            for (int i = 0; i < 4; i++) {
                float p = Ps[4*ty+i][k];   // broadcast read, conflict-free
                o[i][0] += p * vv.x;
                o[i][1] += p * vv.y;
            }
        }
    }

    // normalize + store
    #pragma unroll
    for (int i = 0; i < 4; i++) {
        float inv = 1.0f / l[i];
        float2 r;
        r.x = o[i][0] * inv;
        r.y = o[i][1] * inv;
        *(float2*)(Ob + (qt*64 + 4*ty + i) * HDIM + 2*tx) = r;
    }
}

// ---------------------------------------------------------------------------
// Output projection: out = O @ wo^T  (same structure as qkv, single W)
// ---------------------------------------------------------------------------
__global__ __launch_bounds__(256) void oproj_kernel(
        const float* __restrict__ wo, float* __restrict__ out) {
    __shared__ float Xs[64][132];
    __shared__ float Ws[128][20];
    int tid = threadIdx.x;
    int r0 = blockIdx.x * 64;

    #pragma unroll
    for (int it = 0; it < 8; it++) {
        int idx = tid + it * 256;
        int rl = idx >> 5, d4 = idx & 31;
        float4 x = *(const float4*)(g_o + (long)(r0 + rl) * DMODEL + 4*d4);
        *(float4*)&Xs[rl][4*d4] = x;
    }

    int ty = tid >> 4, tx = tid & 15;
    for (int ch = 0; ch < 8; ch++) {
        int c0 = ch * 16;
        __syncthreads();
        #pragma unroll
        for (int it = 0; it < 2; it++) {
            int idx = tid + it * 256;
            int e  = idx & 15;
            int k4 = idx >> 4;
            float4 w4 = *(const float4*)(wo + (c0 + e) * DMODEL + 4*k4);
            Ws[4*k4+0][e] = w4.x; Ws[4*k4+1][e] = w4.y;
            Ws[4*k4+2][e] = w4.z; Ws[4*k4+3][e] = w4.w;
        }
        __syncthreads();
        float acc0 = 0.f, acc1 = 0.f, acc2 = 0.f, acc3 = 0.f;
        #pragma unroll 16
        for (int k = 0; k < DMODEL; k++) {
            float wval = Ws[k][tx];
            acc0 += Xs[4*ty+0][k] * wval;
            acc1 += Xs[4*ty+1][k] * wval;
            acc2 += Xs[4*ty+2][k] * wval;
            acc3 += Xs[4*ty+3][k] * wval;
        }
        out[(r0 + 4*ty + 0) * DMODEL + c0 + tx] = acc0;
        out[(r0 + 4*ty + 1) * DMODEL + c0 + tx] = acc1;
        out[(r0 + 4*ty + 2) * DMODEL + c0 + tx] = acc2;
        out[(r0 + 4*ty + 3) * DMODEL + c0 + tx] = acc3;
    }
}

extern "C" void kernel_launch(void* const* d_in, const int* in_sizes, int n_in,
                              void* d_out, int out_size) {
    const int*   seq = (const int*)d_in[0];
    const float* emb = (const float*)d_in[1];
    const float* wq  = (const float*)d_in[2];
    const float* wk  = (const float*)d_in[3];
    const float* wv  = (const float*)d_in[4];
    const float* wo  = (const float*)d_in[5];
    float* out = (float*)d_out;

    pe_kernel<<<(SLEN*(DMODEL/2) + 255)/256, 256>>>();
    qkv_kernel<<<NROW/64, 256>>>(seq, emb, wq, wk, wv);
    attn_kernel<<<dim3(SLEN/64, NHB), 256>>>();
    oproj_kernel<<<NROW/64, 256>>>(wo, out);
}

// round 4
// speedup vs baseline: 1.6930x; 1.6919x over previous
#include <cuda_runtime.h>
#include <cuda_bf16.h>
#include <math.h>
#include <stdint.h>

#define BATCH 2
#define SLEN 4096
#define DMODEL 128
#define NHEAD 4
#define HDIM 32
#define NROW (BATCH*SLEN)   // 8192
#define NHB  (BATCH*NHEAD)  // 8

// Scratch (device globals — no allocation allowed)
__device__ float g_pe[SLEN*DMODEL];
__device__ float g_q[BATCH*SLEN*DMODEL];
__device__ float g_k[BATCH*SLEN*DMODEL];
__device__ float g_v[BATCH*SLEN*DMODEL];
__device__ float g_o[BATCH*SLEN*DMODEL];

// ---------------------------------------------------------------------------
// helpers
// ---------------------------------------------------------------------------
// pack two floats -> bf16x2 hi (e in low half, o in high) + bf16x2 residual
__device__ __forceinline__ void split2(float e, float o, uint32_t& hi, uint32_t& lo) {
    uint32_t h;
    asm("cvt.rn.bf16x2.f32 %0, %1, %2;" : "=r"(h) : "f"(o), "f"(e));
    float eh = __uint_as_float(h << 16);
    float oh = __uint_as_float(h & 0xffff0000u);
    float el = e - eh, ol = o - oh;
    uint32_t l;
    asm("cvt.rn.bf16x2.f32 %0, %1, %2;" : "=r"(l) : "f"(ol), "f"(el));
    hi = h; lo = l;
}

__device__ __forceinline__ void split1(float x, uint16_t& h, uint16_t& l) {
    __nv_bfloat16 bh = __float2bfloat16(x);
    float r = x - __bfloat162float(bh);
    __nv_bfloat16 bl = __float2bfloat16(r);
    h = *(uint16_t*)&bh;
    l = *(uint16_t*)&bl;
}

// D (in-place C) += A * B, m16n8k16 bf16 -> f32
__device__ __forceinline__ void mma_bf16(float d[4], const uint32_t a[4], const uint32_t b[2]) {
    asm volatile(
        "mma.sync.aligned.m16n8k16.row.col.f32.bf16.bf16.f32 "
        "{%0,%1,%2,%3},{%4,%5,%6,%7},{%8,%9},{%0,%1,%2,%3};"
        : "+f"(d[0]), "+f"(d[1]), "+f"(d[2]), "+f"(d[3])
        : "r"(a[0]), "r"(a[1]), "r"(a[2]), "r"(a[3]), "r"(b[0]), "r"(b[1]));
}

// ---------------------------------------------------------------------------
// Positional encoding
// ---------------------------------------------------------------------------
__global__ void pe_kernel() {
    int idx = blockIdx.x * blockDim.x + threadIdx.x;
    if (idx >= SLEN * (DMODEL/2)) return;
    int s = idx / (DMODEL/2);
    int i = idx % (DMODEL/2);
    float e = (2.0f * (float)i) / (float)DMODEL;
    double divd = pow(10000.0, (double)e);
    float fdiv = (float)divd;
    float a = (float)s / fdiv;
    double ad = (double)a;
    g_pe[s*DMODEL + 2*i]     = (float)sin(ad);
    g_pe[s*DMODEL + 2*i + 1] = (float)cos(ad);
}

// ---------------------------------------------------------------------------
// QKV projection (fp32 path, proven)
// ---------------------------------------------------------------------------
__global__ __launch_bounds__(256) void qkv_kernel(
        const int* __restrict__ seq, const float* __restrict__ emb,
        const float* __restrict__ wq, const float* __restrict__ wk,
        const float* __restrict__ wv) {
    __shared__ float Xs[64][132];
    __shared__ float Ws[128][20];
    int tid = threadIdx.x;
    int r0 = blockIdx.x * 64;

    #pragma unroll
    for (int it = 0; it < 8; it++) {
        int idx = tid + it * 256;
        int rl = idx >> 5, d4 = idx & 31;
        int row = r0 + rl;
        int tok = seq[row];
        int sp = row & (SLEN - 1);
        float4 e4 = *(const float4*)(emb + (long)tok * DMODEL + 4*d4);
        float4 p4 = *(const float4*)(g_pe + sp * DMODEL + 4*d4);
        float4 x;
        x.x = e4.x + p4.x; x.y = e4.y + p4.y;
        x.z = e4.z + p4.z; x.w = e4.w + p4.w;
        *(float4*)&Xs[rl][4*d4] = x;
    }

    int ty = tid >> 4, tx = tid & 15;
    for (int w = 0; w < 3; w++) {
        const float* W = (w == 0) ? wq : ((w == 1) ? wk : wv);
        float* out = (w == 0) ? g_q : ((w == 1) ? g_k : g_v);
        for (int ch = 0; ch < 8; ch++) {
            int c0 = ch * 16;
            __syncthreads();
            #pragma unroll
            for (int it = 0; it < 2; it++) {
                int idx = tid + it * 256;
                int e  = idx & 15;
                int k4 = idx >> 4;
                float4 w4 = *(const float4*)(W + (c0 + e) * DMODEL + 4*k4);
                Ws[4*k4+0][e] = w4.x; Ws[4*k4+1][e] = w4.y;
                Ws[4*k4+2][e] = w4.z; Ws[4*k4+3][e] = w4.w;
            }
            __syncthreads();
            float acc0 = 0.f, acc1 = 0.f, acc2 = 0.f, acc3 = 0.f;
            #pragma unroll 16
            for (int k = 0; k < DMODEL; k++) {
                float wval = Ws[k][tx];
                acc0 += Xs[4*ty+0][k] * wval;
                acc1 += Xs[4*ty+1][k] * wval;
                acc2 += Xs[4*ty+2][k] * wval;
                acc3 += Xs[4*ty+3][k] * wval;
            }
            out[(r0 + 4*ty + 0) * DMODEL + c0 + tx] = acc0;
            out[(r0 + 4*ty + 1) * DMODEL + c0 + tx] = acc1;
            out[(r0 + 4*ty + 2) * DMODEL + c0 + tx] = acc2;
            out[(r0 + 4*ty + 3) * DMODEL + c0 + tx] = acc3;
        }
    }
}

// ---------------------------------------------------------------------------
// HMMA flash attention (mma.sync m16n8k16 bf16, hi/lo split, no-max softmax)
// Block = (head hb, 128-row q tile). 256 threads = 8 warps, warp w owns rows
// 16w..16w+15. Fragment conventions (PTX m16n8k16): g=lane/4, u=lane%4.
//   A: r0={A[g][2u],A[g][2u+1]}, r1={A[g+8][..]}, r2={A[g][2u+8]..}, r3={A[g+8][2u+8]..}
//   B: r0={B[2u][g],B[2u+1][g]}, r1={B[2u+8][g],B[2u+9][g]}
//   C: c0=C[g][2u], c1=C[g][2u+1], c2=C[g+8][2u], c3=C[g+8][2u+1]
// SMEM: Kh/Kl [128 keys][80B stride] (d-major rows); Vth/Vtl transposed
//   [32 hd][272B stride] (key-major rows). Both strides conflict-free for the
//   (g quads x u) B-frag LDS.32 pattern.
// ---------------------------------------------------------------------------
#define KH   0
#define KL   10240
#define VTH  20480
#define VTL  29184
#define ATT_SMEM 37888

__global__ __launch_bounds__(256) void attn_mma_kernel() {
    __shared__ char smem[ATT_SMEM];
    int tid = threadIdx.x;
    int w = tid >> 5, lane = tid & 31;
    int g = lane >> 2, u = lane & 3;

    // snake order: balance heavy/light q tiles across waves
    int x = blockIdx.x;
    int qt = (x & 1) ? (x >> 1) : (31 - (x >> 1));
    int hb = blockIdx.y;

    const float* Qb = g_q + (long)hb * SLEN * HDIM;
    const float* Kb = g_k + (long)hb * SLEN * HDIM;
    const float* Vb = g_v + (long)hb * SLEN * HDIM;
    float* Ob = g_o + (long)hb * SLEN * HDIM;

    const float scale = 0.17677669529663687f;  // 1/sqrt(32)

    // ---- Q A-fragments (direct from gmem, scaled + split) ----
    uint32_t qh[2][4], ql[2][4];
    int r0 = qt * 128 + 16 * w + g;
    const float* Q0 = Qb + (long)r0 * HDIM;
    const float* Q1 = Q0 + 8 * HDIM;
    #pragma unroll
    for (int kt = 0; kt < 2; kt++) {
        int c = 16 * kt + 2 * u;
        float2 x00 = *(const float2*)(Q0 + c);
        float2 x01 = *(const float2*)(Q0 + c + 8);
        float2 x10 = *(const float2*)(Q1 + c);
        float2 x11 = *(const float2*)(Q1 + c + 8);
        split2(x00.x * scale, x00.y * scale, qh[kt][0], ql[kt][0]);
        split2(x10.x * scale, x10.y * scale, qh[kt][1], ql[kt][1]);
        split2(x01.x * scale, x01.y * scale, qh[kt][2], ql[kt][2]);
        split2(x11.x * scale, x11.y * scale, qh[kt][3], ql[kt][3]);
    }

    float O[4][4];
    #pragma unroll
    for (int jo = 0; jo < 4; jo++)
        #pragma unroll
        for (int e = 0; e < 4; e++) O[jo][e] = 0.f;
    float lsum0 = 0.f, lsum1 = 0.f;

    for (int jt = 0; jt <= qt; jt++) {
        __syncthreads();
        // ---- stage K (hi/lo, d-major) and V (hi/lo, transposed) ----
        const float4* Ksrc = (const float4*)(Kb + (long)jt * 128 * HDIM);
        const float4* Vsrc = (const float4*)(Vb + (long)jt * 128 * HDIM);
        #pragma unroll
        for (int it = 0; it < 4; it++) {
            int gi = tid + it * 256;
            int key = gi >> 3, c4 = gi & 7;
            float4 kv = Ksrc[gi];
            uint32_t h0, l0, h1, l1;
            split2(kv.x, kv.y, h0, l0);
            split2(kv.z, kv.w, h1, l1);
            *(uint2*)(smem + KH + key * 80 + c4 * 8) = make_uint2(h0, h1);
            *(uint2*)(smem + KL + key * 80 + c4 * 8) = make_uint2(l0, l1);
            float4 vv = Vsrc[gi];
            float vals[4] = {vv.x, vv.y, vv.z, vv.w};
            #pragma unroll
            for (int i2 = 0; i2 < 4; i2++) {
                uint16_t hh, ll;
                split1(vals[i2], hh, ll);
                int hd = 4 * c4 + i2;
                *(uint16_t*)(smem + VTH + hd * 272 + 2 * key) = hh;
                *(uint16_t*)(smem + VTL + hd * 272 + 2 * key) = ll;
            }
        }
        __syncthreads();

        // ---- S = Q K^T : 16 n-tiles x (2 ksteps x 3 split terms) ----
        float s[16][4];
        #pragma unroll
        for (int j = 0; j < 16; j++) {
            const char* kr = smem + (8 * j + g) * 80 + 4 * u;
            uint32_t bh0[2] = { *(const uint32_t*)(kr + KH),      *(const uint32_t*)(kr + KH + 16) };
            uint32_t bh1[2] = { *(const uint32_t*)(kr + KH + 32), *(const uint32_t*)(kr + KH + 48) };
            uint32_t bl0[2] = { *(const uint32_t*)(kr + KL),      *(const uint32_t*)(kr + KL + 16) };
            uint32_t bl1[2] = { *(const uint32_t*)(kr + KL + 32), *(const uint32_t*)(kr + KL + 48) };
            s[j][0] = 0.f; s[j][1] = 0.f; s[j][2] = 0.f; s[j][3] = 0.f;
            mma_bf16(s[j], qh[0], bh0);
            mma_bf16(s[j], qh[1], bh1);
            mma_bf16(s[j], qh[0], bl0);
            mma_bf16(s[j], qh[1], bl1);
            mma_bf16(s[j], ql[0], bh0);
            mma_bf16(s[j], ql[1], bh1);
        }

        // ---- softmax (no max subtraction; scores bounded) ----
        bool diag = (jt == qt);
        int rloc0 = 16 * w + g;
        #pragma unroll
        for (int j = 0; j < 16; j++) {
            #pragma unroll
            for (int e = 0; e < 4; e++) {
                float p = __expf(fabsf(s[j][e]));
                if (diag) {
                    int col = 8 * j + 2 * u + (e & 1);
                    int row = rloc0 + ((e >= 2) ? 8 : 0);
                    if (col > row) p = 0.f;
                }
                s[j][e] = p;
            }
            lsum0 += s[j][0] + s[j][1];
            lsum1 += s[j][2] + s[j][3];
        }

        // ---- O += P V : C-frags -> A-frags in registers, V from smem ----
        #pragma unroll
        for (int kt = 0; kt < 8; kt++) {
            uint32_t ah[4], al[4];
            split2(s[2*kt][0],   s[2*kt][1],   ah[0], al[0]);
            split2(s[2*kt][2],   s[2*kt][3],   ah[1], al[1]);
            split2(s[2*kt+1][0], s[2*kt+1][1], ah[2], al[2]);
            split2(s[2*kt+1][2], s[2*kt+1][3], ah[3], al[3]);
            #pragma unroll
            for (int jo = 0; jo < 4; jo++) {
                const char* vr = smem + (8 * jo + g) * 272 + 32 * kt + 4 * u;
                uint32_t bh[2] = { *(const uint32_t*)(vr + VTH), *(const uint32_t*)(vr + VTH + 16) };
                uint32_t bl[2] = { *(const uint32_t*)(vr + VTL), *(const uint32_t*)(vr + VTL + 16) };
                mma_bf16(O[jo], ah, bh);
                mma_bf16(O[jo], ah, bl);
                mma_bf16(O[jo], al, bh);
            }
        }
    }

    // ---- row sums across the quad, normalize, store ----
    lsum0 += __shfl_xor_sync(0xffffffffu, lsum0, 1);
    lsum0 += __shfl_xor_sync(0xffffffffu, lsum0, 2);
    lsum1 += __shfl_xor_sync(0xffffffffu, lsum1, 1);
    lsum1 += __shfl_xor_sync(0xffffffffu, lsum1, 2);
    float inv0 = 1.0f / lsum0;
    float inv1 = 1.0f / lsum1;

    float* O0 = Ob + (long)r0 * HDIM;
    float* O1 = O0 + 8 * HDIM;
    #pragma unroll
    for (int jo = 0; jo < 4; jo++) {
        *(float2*)(O0 + 8 * jo + 2 * u) = make_float2(O[jo][0] * inv0, O[jo][1] * inv0);
        *(float2*)(O1 + 8 * jo + 2 * u) = make_float2(O[jo][2] * inv1, O[jo][3] * inv1);
    }
}

// ---------------------------------------------------------------------------
// Output projection (fp32 path, proven)
// ---------------------------------------------------------------------------
__global__ __launch_bounds__(256) void oproj_kernel(
        const float* __restrict__ wo, float* __restrict__ out) {
    __shared__ float Xs[64][132];
    __shared__ float Ws[128][20];
    int tid = threadIdx.x;
    int r0 = blockIdx.x * 64;

    #pragma unroll
    for (int it = 0; it < 8; it++) {
        int idx = tid + it * 256;
        int rl = idx >> 5, d4 = idx & 31;
        float4 x = *(const float4*)(g_o + (long)(r0 + rl) * DMODEL + 4*d4);
        *(float4*)&Xs[rl][4*d4] = x;
    }

    int ty = tid >> 4, tx = tid & 15;
    for (int ch = 0; ch < 8; ch++) {
        int c0 = ch * 16;
        __syncthreads();
        #pragma unroll
        for (int it = 0; it < 2; it++) {
            int idx = tid + it * 256;
            int e  = idx & 15;
            int k4 = idx >> 4;
            float4 w4 = *(const float4*)(wo + (c0 + e) * DMODEL + 4*k4);
            Ws[4*k4+0][e] = w4.x; Ws[4*k4+1][e] = w4.y;
            Ws[4*k4+2][e] = w4.z; Ws[4*k4+3][e] = w4.w;
        }
        __syncthreads();
        float acc0 = 0.f, acc1 = 0.f, acc2 = 0.f, acc3 = 0.f;
        #pragma unroll 16
        for (int k = 0; k < DMODEL; k++) {
            float wval = Ws[k][tx];
            acc0 += Xs[4*ty+0][k] * wval;
            acc1 += Xs[4*ty+1][k] * wval;
            acc2 += Xs[4*ty+2][k] * wval;
            acc3 += Xs[4*ty+3][k] * wval;
        }
        out[(r0 + 4*ty + 0) * DMODEL + c0 + tx] = acc0;
        out[(r0 + 4*ty + 1) * DMODEL + c0 + tx] = acc1;
        out[(r0 + 4*ty + 2) * DMODEL + c0 + tx] = acc2;
        out[(r0 + 4*ty + 3) * DMODEL + c0 + tx] = acc3;
    }
}

extern "C" void kernel_launch(void* const* d_in, const int* in_sizes, int n_in,
                              void* d_out, int out_size) {
    const int*   seq = (const int*)d_in[0];
    const float* emb = (const float*)d_in[1];
    const float* wq  = (const float*)d_in[2];
    const float* wk  = (const float*)d_in[3];
    const float* wv  = (const float*)d_in[4];
    const float* wo  = (const float*)d_in[5];
    float* out = (float*)d_out;

    pe_kernel<<<(SLEN*(DMODEL/2) + 255)/256, 256>>>();
    qkv_kernel<<<NROW/64, 256>>>(seq, emb, wq, wk, wv);
    attn_mma_kernel<<<dim3(32, NHB), 256>>>();
    oproj_kernel<<<NROW/64, 256>>>(wo, out);
}

// round 5
// speedup vs baseline: 2.0312x; 1.1998x over previous
#include <cuda_runtime.h>
#include <cuda_bf16.h>
#include <math.h>
#include <stdint.h>

#define BATCH 2
#define SLEN 4096
#define DMODEL 128
#define NHEAD 4
#define HDIM 32
#define NROW (BATCH*SLEN)   // 8192
#define NHB  (BATCH*NHEAD)  // 8

// Scratch (device globals — no allocation allowed)
__device__ float g_pe[SLEN*DMODEL];
// pre-split bf16 hi/lo buffers (flat [8192][128]; head-flat view is same memory)
__device__ __nv_bfloat16 g_qh[NROW*DMODEL], g_ql[NROW*DMODEL];
__device__ __nv_bfloat16 g_kh[NROW*DMODEL], g_kl[NROW*DMODEL];
__device__ __nv_bfloat16 g_vh[NROW*DMODEL], g_vl[NROW*DMODEL];
__device__ __nv_bfloat16 g_oh[NROW*DMODEL], g_ol[NROW*DMODEL];
__device__ __nv_bfloat16 g_wh[4*DMODEL*DMODEL], g_wl[4*DMODEL*DMODEL];

// ---------------------------------------------------------------------------
// helpers
// ---------------------------------------------------------------------------
// pack two floats -> bf16x2 hi (e in low half, o in high) + bf16x2 residual
__device__ __forceinline__ void split2(float e, float o, uint32_t& hi, uint32_t& lo) {
    uint32_t h;
    asm("cvt.rn.bf16x2.f32 %0, %1, %2;" : "=r"(h) : "f"(o), "f"(e));
    float eh = __uint_as_float(h << 16);
    float oh = __uint_as_float(h & 0xffff0000u);
    float el = e - eh, ol = o - oh;
    uint32_t l;
    asm("cvt.rn.bf16x2.f32 %0, %1, %2;" : "=r"(l) : "f"(ol), "f"(el));
    hi = h; lo = l;
}

__device__ __forceinline__ void split1(float x, __nv_bfloat16& h, __nv_bfloat16& l) {
    h = __float2bfloat16(x);
    l = __float2bfloat16(x - __bfloat162float(h));
}

// D (in-place C) += A * B, m16n8k16 bf16 -> f32
__device__ __forceinline__ void mma_bf16(float d[4], const uint32_t a[4], const uint32_t b[2]) {
    asm volatile(
        "mma.sync.aligned.m16n8k16.row.col.f32.bf16.bf16.f32 "
        "{%0,%1,%2,%3},{%4,%5,%6,%7},{%8,%9},{%0,%1,%2,%3};"
        : "+f"(d[0]), "+f"(d[1]), "+f"(d[2]), "+f"(d[3])
        : "r"(a[0]), "r"(a[1]), "r"(a[2]), "r"(a[3]), "r"(b[0]), "r"(b[1]));
}

// ---------------------------------------------------------------------------
// Positional encoding
// ---------------------------------------------------------------------------
__global__ void pe_kernel() {
    int idx = blockIdx.x * blockDim.x + threadIdx.x;
    if (idx >= SLEN * (DMODEL/2)) return;
    int s = idx / (DMODEL/2);
    int i = idx % (DMODEL/2);
    float e = (2.0f * (float)i) / (float)DMODEL;
    double divd = exp2((double)e * 13.287712379549449);  // 10000^e
    float fdiv = (float)divd;
    float a = (float)s / fdiv;                            // fp32 like jax
    double sv, cv;
    sincos((double)a, &sv, &cv);
    g_pe[s*DMODEL + 2*i]     = (float)sv;
    g_pe[s*DMODEL + 2*i + 1] = (float)cv;
}

// ---------------------------------------------------------------------------
// Split the 4 weight matrices into bf16 hi/lo
// ---------------------------------------------------------------------------
__global__ void wsplit_kernel(const float* __restrict__ wq, const float* __restrict__ wk,
                              const float* __restrict__ wv, const float* __restrict__ wo) {
    int idx = blockIdx.x * blockDim.x + threadIdx.x;   // 0..16383
    const float* Ws[4] = {wq, wk, wv, wo};
    #pragma unroll
    for (int m = 0; m < 4; m++) {
        __nv_bfloat16 h, l;
        split1(Ws[m][idx], h, l);
        g_wh[m * DMODEL * DMODEL + idx] = h;
        g_wl[m * DMODEL * DMODEL + idx] = l;
    }
}

// ---------------------------------------------------------------------------
// QKV projection via HMMA. Warp job: 16 rows (m16) x 64 cols (8 n-tiles) for
// all 3 matrices. A-frags built once from emb+pe (split to hi/lo in regs).
// B-frags are uint32 pairs loaded directly from pre-split W (row-major [n][k]
// == exactly the "col"-B fragment pair). Outputs stored pre-split (Q scaled).
// grid: 256 blocks x 128 thr (4 warps): bid>>1 = 64-row block, bid&1 = n half.
// ---------------------------------------------------------------------------
__global__ __launch_bounds__(128) void qkv_mma_kernel(
        const int* __restrict__ seq, const float* __restrict__ emb) {
    int tid = threadIdx.x;
    int w = tid >> 5, lane = tid & 31;
    int g = lane >> 2, u = lane & 3;
    int m0 = (blockIdx.x >> 1) * 64 + 16 * w;
    int jbase = (blockIdx.x & 1) * 8;

    int ra = m0 + g, rb = ra + 8;
    int tok_a = seq[ra], tok_b = seq[rb];
    int sa = ra & (SLEN - 1), sb = rb & (SLEN - 1);
    const float* Ea = emb + (long)tok_a * DMODEL;
    const float* Eb = emb + (long)tok_b * DMODEL;
    const float* Pa = g_pe + sa * DMODEL;
    const float* Pb = g_pe + sb * DMODEL;

    // A-frags (8 ksteps), hi/lo
    uint32_t xh[8][4], xl[8][4];
    #pragma unroll
    for (int ks = 0; ks < 8; ks++) {
        int c = 16 * ks + 2 * u;
        float2 e0, p0;
        e0 = *(const float2*)(Ea + c);     p0 = *(const float2*)(Pa + c);
        split2(e0.x + p0.x, e0.y + p0.y, xh[ks][0], xl[ks][0]);
        e0 = *(const float2*)(Eb + c);     p0 = *(const float2*)(Pb + c);
        split2(e0.x + p0.x, e0.y + p0.y, xh[ks][1], xl[ks][1]);
        e0 = *(const float2*)(Ea + c + 8); p0 = *(const float2*)(Pa + c + 8);
        split2(e0.x + p0.x, e0.y + p0.y, xh[ks][2], xl[ks][2]);
        e0 = *(const float2*)(Eb + c + 8); p0 = *(const float2*)(Pb + c + 8);
        split2(e0.x + p0.x, e0.y + p0.y, xh[ks][3], xl[ks][3]);
    }

    const float scale = 0.17677669529663687f;  // 1/sqrt(32) folded into Q

    #pragma unroll
    for (int mat = 0; mat < 3; mat++) {
        const __nv_bfloat16* wh = g_wh + mat * DMODEL * DMODEL;
        const __nv_bfloat16* wl = g_wl + mat * DMODEL * DMODEL;
        __nv_bfloat16* oh = (mat == 0) ? g_qh : ((mat == 1) ? g_kh : g_vh);
        __nv_bfloat16* ol = (mat == 0) ? g_ql : ((mat == 1) ? g_kl : g_vl);

        float acc[8][4];
        #pragma unroll
        for (int j = 0; j < 8; j++)
            #pragma unroll
            for (int e = 0; e < 4; e++) acc[j][e] = 0.f;

        #pragma unroll
        for (int ks = 0; ks < 8; ks++) {
            #pragma unroll
            for (int j = 0; j < 8; j++) {
                int n = (jbase + j) * 8 + g;
                const uint32_t* bhp = (const uint32_t*)(wh + n * DMODEL + 16 * ks + 2 * u);
                const uint32_t* blp = (const uint32_t*)(wl + n * DMODEL + 16 * ks + 2 * u);
                uint32_t bh[2] = { bhp[0], bhp[4] };
                uint32_t bl[2] = { blp[0], blp[4] };
                mma_bf16(acc[j], xh[ks], bh);
                mma_bf16(acc[j], xl[ks], bh);
                mma_bf16(acc[j], xh[ks], bl);
            }
        }

        float sc = (mat == 0) ? scale : 1.0f;
        #pragma unroll
        for (int j = 0; j < 8; j++) {
            int cbase = (jbase + j) * 8 + 2 * u;
            uint32_t h0, l0;
            split2(acc[j][0] * sc, acc[j][1] * sc, h0, l0);
            *(uint32_t*)(oh + (long)ra * DMODEL + cbase) = h0;
            *(uint32_t*)(ol + (long)ra * DMODEL + cbase) = l0;
            split2(acc[j][2] * sc, acc[j][3] * sc, h0, l0);
            *(uint32_t*)(oh + (long)rb * DMODEL + cbase) = h0;
            *(uint32_t*)(ol + (long)rb * DMODEL + cbase) = l0;
        }
    }
}

// ---------------------------------------------------------------------------
// HMMA flash attention on pre-split bf16 inputs.
// Block = (head hb, 128-row q tile). 256 thr = 8 warps, warp w rows 16w..+15.
// Q a-frags: direct uint32 gmem loads. K staged hi/lo [key][80B]; V staged
// transposed hi/lo [hd][272B]. P split in regs feeds PV directly (FA2 C->A).
// No-max softmax: scores |.| bounded -> O accumulates with no rescaling.
// ---------------------------------------------------------------------------
#define KH   0
#define KL   10240
#define VTH  20480
#define VTL  29184
#define ATT_SMEM 37888

__global__ __launch_bounds__(256) void attn_mma_kernel() {
    __shared__ char smem[ATT_SMEM];
    int tid = threadIdx.x;
    int w = tid >> 5, lane = tid & 31;
    int g = lane >> 2, u = lane & 3;

    int x = blockIdx.x;
    int qt = (x & 1) ? (x >> 1) : (31 - (x >> 1));   // snake balance
    int hb = blockIdx.y;
    long hoff = (long)hb * SLEN * HDIM;

    const __nv_bfloat16* Qbh = g_qh + hoff;
    const __nv_bfloat16* Qbl = g_ql + hoff;
    const __nv_bfloat16* Kbh = g_kh + hoff;
    const __nv_bfloat16* Kbl = g_kl + hoff;
    const __nv_bfloat16* Vbh = g_vh + hoff;
    const __nv_bfloat16* Vbl = g_vl + hoff;

    // ---- Q A-fragments (pre-scaled, pre-split in gmem) ----
    int r0 = qt * 128 + 16 * w + g;
    uint32_t qh[2][4], ql[2][4];
    #pragma unroll
    for (int kt = 0; kt < 2; kt++) {
        int c = 16 * kt + 2 * u;
        qh[kt][0] = *(const uint32_t*)(Qbh + (long)r0 * HDIM + c);
        qh[kt][1] = *(const uint32_t*)(Qbh + (long)(r0 + 8) * HDIM + c);
        qh[kt][2] = *(const uint32_t*)(Qbh + (long)r0 * HDIM + c + 8);
        qh[kt][3] = *(const uint32_t*)(Qbh + (long)(r0 + 8) * HDIM + c + 8);
        ql[kt][0] = *(const uint32_t*)(Qbl + (long)r0 * HDIM + c);
        ql[kt][1] = *(const uint32_t*)(Qbl + (long)(r0 + 8) * HDIM + c);
        ql[kt][2] = *(const uint32_t*)(Qbl + (long)r0 * HDIM + c + 8);
        ql[kt][3] = *(const uint32_t*)(Qbl + (long)(r0 + 8) * HDIM + c + 8);
    }

    float O[4][4];
    #pragma unroll
    for (int jo = 0; jo < 4; jo++)
        #pragma unroll
        for (int e = 0; e < 4; e++) O[jo][e] = 0.f;
    float lsum0 = 0.f, lsum1 = 0.f;

    for (int jt = 0; jt <= qt; jt++) {
        __syncthreads();
        long toff = (long)jt * 128 * HDIM;
        // ---- stage K (copy) ----
        #pragma unroll
        for (int it = 0; it < 2; it++) {
            int gi = tid + it * 256;             // 512 uint4 per buffer
            int key = gi >> 2, q4 = gi & 3;
            *(uint4*)(smem + KH + key * 80 + 16 * q4) =
                *(const uint4*)(Kbh + toff + key * HDIM + 8 * q4);
            *(uint4*)(smem + KL + key * 80 + 16 * q4) =
                *(const uint4*)(Kbl + toff + key * HDIM + 8 * q4);
        }
        // ---- stage V (transpose) ----
        #pragma unroll
        for (int it = 0; it < 8; it++) {
            int gi = tid + it * 256;             // 2048 uint32 per buffer
            int key = gi >> 4, c = gi & 15;
            uint32_t dh = *(const uint32_t*)(Vbh + toff + key * HDIM + 2 * c);
            uint32_t dl = *(const uint32_t*)(Vbl + toff + key * HDIM + 2 * c);
            *(uint16_t*)(smem + VTH + (2*c)   * 272 + 2 * key) = (uint16_t)dh;
            *(uint16_t*)(smem + VTH + (2*c+1) * 272 + 2 * key) = (uint16_t)(dh >> 16);
            *(uint16_t*)(smem + VTL + (2*c)   * 272 + 2 * key) = (uint16_t)dl;
            *(uint16_t*)(smem + VTL + (2*c+1) * 272 + 2 * key) = (uint16_t)(dl >> 16);
        }
        __syncthreads();

        // ---- S = Q K^T ----
        float s[16][4];
        #pragma unroll
        for (int j = 0; j < 16; j++) {
            const char* kr = smem + (8 * j + g) * 80 + 4 * u;
            uint32_t bh0[2] = { *(const uint32_t*)(kr + KH),      *(const uint32_t*)(kr + KH + 16) };
            uint32_t bh1[2] = { *(const uint32_t*)(kr + KH + 32), *(const uint32_t*)(kr + KH + 48) };
            uint32_t bl0[2] = { *(const uint32_t*)(kr + KL),      *(const uint32_t*)(kr + KL + 16) };
            uint32_t bl1[2] = { *(const uint32_t*)(kr + KL + 32), *(const uint32_t*)(kr + KL + 48) };
            s[j][0] = 0.f; s[j][1] = 0.f; s[j][2] = 0.f; s[j][3] = 0.f;
            mma_bf16(s[j], qh[0], bh0);
            mma_bf16(s[j], qh[1], bh1);
            mma_bf16(s[j], qh[0], bl0);
            mma_bf16(s[j], qh[1], bl1);
            mma_bf16(s[j], ql[0], bh0);
            mma_bf16(s[j], ql[1], bh1);
        }

        // ---- softmax (no max subtraction; scores bounded) ----
        bool diag = (jt == qt);
        int rloc0 = 16 * w + g;
        #pragma unroll
        for (int j = 0; j < 16; j++) {
            #pragma unroll
            for (int e = 0; e < 4; e++) {
                float p = __expf(fabsf(s[j][e]));
                if (diag) {
                    int col = 8 * j + 2 * u + (e & 1);
                    int row = rloc0 + ((e >= 2) ? 8 : 0);
                    if (col > row) p = 0.f;
                }
                s[j][e] = p;
            }
            lsum0 += s[j][0] + s[j][1];
            lsum1 += s[j][2] + s[j][3];
        }

        // ---- O += P V ----
        #pragma unroll
        for (int kt = 0; kt < 8; kt++) {
            uint32_t ah[4], al[4];
            split2(s[2*kt][0],   s[2*kt][1],   ah[0], al[0]);
            split2(s[2*kt][2],   s[2*kt][3],   ah[1], al[1]);
            split2(s[2*kt+1][0], s[2*kt+1][1], ah[2], al[2]);
            split2(s[2*kt+1][2], s[2*kt+1][3], ah[3], al[3]);
            #pragma unroll
            for (int jo = 0; jo < 4; jo++) {
                const char* vr = smem + (8 * jo + g) * 272 + 32 * kt + 4 * u;
                uint32_t bh[2] = { *(const uint32_t*)(vr + VTH), *(const uint32_t*)(vr + VTH + 16) };
                uint32_t bl[2] = { *(const uint32_t*)(vr + VTL), *(const uint32_t*)(vr + VTL + 16) };
                mma_bf16(O[jo], ah, bh);
                mma_bf16(O[jo], ah, bl);
                mma_bf16(O[jo], al, bh);
            }
        }
    }

    // ---- normalize + split-store O to bf16 hi/lo ----
    lsum0 += __shfl_xor_sync(0xffffffffu, lsum0, 1);
    lsum0 += __shfl_xor_sync(0xffffffffu, lsum0, 2);
    lsum1 += __shfl_xor_sync(0xffffffffu, lsum1, 1);
    lsum1 += __shfl_xor_sync(0xffffffffu, lsum1, 2);
    float inv0 = 1.0f / lsum0;
    float inv1 = 1.0f / lsum1;

    __nv_bfloat16* Oh = g_oh + hoff;
    __nv_bfloat16* Ol = g_ol + hoff;
    #pragma unroll
    for (int jo = 0; jo < 4; jo++) {
        int cbase = 8 * jo + 2 * u;
        uint32_t h0, l0;
        split2(O[jo][0] * inv0, O[jo][1] * inv0, h0, l0);
        *(uint32_t*)(Oh + (long)r0 * HDIM + cbase) = h0;
        *(uint32_t*)(Ol + (long)r0 * HDIM + cbase) = l0;
        split2(O[jo][2] * inv1, O[jo][3] * inv1, h0, l0);
        *(uint32_t*)(Oh + (long)(r0 + 8) * HDIM + cbase) = h0;
        *(uint32_t*)(Ol + (long)(r0 + 8) * HDIM + cbase) = l0;
    }
}

// ---------------------------------------------------------------------------
// Output projection via HMMA (register-resident; A from pre-split O, B from
// pre-split wo). Same geometry as qkv_mma.
// ---------------------------------------------------------------------------
__global__ __launch_bounds__(128) void oproj_mma_kernel(float* __restrict__ out) {
    int tid = threadIdx.x;
    int w = tid >> 5, lane = tid & 31;
    int g = lane >> 2, u = lane & 3;
    int m0 = (blockIdx.x >> 1) * 64 + 16 * w;
    int jbase = (blockIdx.x & 1) * 8;

    int ra = m0 + g, rb = ra + 8;

    uint32_t xh[8][4], xl[8][4];
    #pragma unroll
    for (int ks = 0; ks < 8; ks++) {
        int c = 16 * ks + 2 * u;
        xh[ks][0] = *(const uint32_t*)(g_oh + (long)ra * DMODEL + c);
        xh[ks][1] = *(const uint32_t*)(g_oh + (long)rb * DMODEL + c);
        xh[ks][2] = *(const uint32_t*)(g_oh + (long)ra * DMODEL + c + 8);
        xh[ks][3] = *(const uint32_t*)(g_oh + (long)rb * DMODEL + c + 8);
        xl[ks][0] = *(const uint32_t*)(g_ol + (long)ra * DMODEL + c);
        xl[ks][1] = *(const uint32_t*)(g_ol + (long)rb * DMODEL + c);
        xl[ks][2] = *(const uint32_t*)(g_ol + (long)ra * DMODEL + c + 8);
        xl[ks][3] = *(const uint32_t*)(g_ol + (long)rb * DMODEL + c + 8);
    }

    const __nv_bfloat16* wh = g_wh + 3 * DMODEL * DMODEL;
    const __nv_bfloat16* wl = g_wl + 3 * DMODEL * DMODEL;

    float acc[8][4];
    #pragma unroll
    for (int j = 0; j < 8; j++)
        #pragma unroll
        for (int e = 0; e < 4; e++) acc[j][e] = 0.f;

    #pragma unroll
    for (int ks = 0; ks < 8; ks++) {
        #pragma unroll
        for (int j = 0; j < 8; j++) {
            int n = (jbase + j) * 8 + g;
            const uint32_t* bhp = (const uint32_t*)(wh + n * DMODEL + 16 * ks + 2 * u);
            const uint32_t* blp = (const uint32_t*)(wl + n * DMODEL + 16 * ks + 2 * u);
            uint32_t bh[2] = { bhp[0], bhp[4] };
            uint32_t bl[2] = { blp[0], blp[4] };
            mma_bf16(acc[j], xh[ks], bh);
            mma_bf16(acc[j], xl[ks], bh);
            mma_bf16(acc[j], xh[ks], bl);
        }
    }

    #pragma unroll
    for (int j = 0; j < 8; j++) {
        int cbase = (jbase + j) * 8 + 2 * u;
        *(float2*)(out + (long)ra * DMODEL + cbase) = make_float2(acc[j][0], acc[j][1]);
        *(float2*)(out + (long)rb * DMODEL + cbase) = make_float2(acc[j][2], acc[j][3]);
    }
}

extern "C" void kernel_launch(void* const* d_in, const int* in_sizes, int n_in,
                              void* d_out, int out_size) {
    const int*   seq = (const int*)d_in[0];
    const float* emb = (const float*)d_in[1];
    const float* wq  = (const float*)d_in[2];
    const float* wk  = (const float*)d_in[3];
    const float* wv  = (const float*)d_in[4];
    const float* wo  = (const float*)d_in[5];
    float* out = (float*)d_out;

    pe_kernel<<<(SLEN*(DMODEL/2) + 255)/256, 256>>>();
    wsplit_kernel<<<(DMODEL*DMODEL + 255)/256, 256>>>(wq, wk, wv, wo);
    qkv_mma_kernel<<<256, 128>>>(seq, emb);
    attn_mma_kernel<<<dim3(32, NHB), 256>>>();
    oproj_mma_kernel<<<256, 128>>>(out);
}

// round 6
// speedup vs baseline: 2.2405x; 1.1030x over previous
#include <cuda_runtime.h>
#include <cuda_bf16.h>
#include <math.h>
#include <stdint.h>

#define BATCH 2
#define SLEN 4096
#define DMODEL 128
#define NHEAD 4
#define HDIM 32
#define NROW (BATCH*SLEN)   // 8192
#define NHB  (BATCH*NHEAD)  // 8

// Scratch (device globals — no allocation allowed)
__device__ float g_pe[SLEN*DMODEL];
__device__ __nv_bfloat16 g_qh[NROW*DMODEL], g_ql[NROW*DMODEL];
__device__ __nv_bfloat16 g_kh[NROW*DMODEL], g_kl[NROW*DMODEL];
__device__ __nv_bfloat16 g_vh[NROW*DMODEL], g_vl[NROW*DMODEL];
__device__ __nv_bfloat16 g_oh[NROW*DMODEL], g_ol[NROW*DMODEL];
__device__ __nv_bfloat16 g_wh[4*DMODEL*DMODEL], g_wl[4*DMODEL*DMODEL];

// ---------------------------------------------------------------------------
// helpers
// ---------------------------------------------------------------------------
__device__ __forceinline__ uint32_t smem_u32(const void* p) {
    uint32_t a;
    asm("{ .reg .u64 t; cvta.to.shared.u64 t, %1; cvt.u32.u64 %0, t; }" : "=r"(a) : "l"(p));
    return a;
}

// pack two floats -> bf16x2 hi (e in low half, o in high) + bf16x2 residual
__device__ __forceinline__ void split2(float e, float o, uint32_t& hi, uint32_t& lo) {
    uint32_t h;
    asm("cvt.rn.bf16x2.f32 %0, %1, %2;" : "=r"(h) : "f"(o), "f"(e));
    float eh = __uint_as_float(h << 16);
    float oh = __uint_as_float(h & 0xffff0000u);
    float el = e - eh, ol = o - oh;
    uint32_t l;
    asm("cvt.rn.bf16x2.f32 %0, %1, %2;" : "=r"(l) : "f"(ol), "f"(el));
    hi = h; lo = l;
}

__device__ __forceinline__ void split1(float x, __nv_bfloat16& h, __nv_bfloat16& l) {
    h = __float2bfloat16(x);
    l = __float2bfloat16(x - __bfloat162float(h));
}

// D (in-place C) += A * B, m16n8k16 bf16 -> f32
__device__ __forceinline__ void mma_bf16(float d[4], const uint32_t a[4], const uint32_t b[2]) {
    asm volatile(
        "mma.sync.aligned.m16n8k16.row.col.f32.bf16.bf16.f32 "
        "{%0,%1,%2,%3},{%4,%5,%6,%7},{%8,%9},{%0,%1,%2,%3};"
        : "+f"(d[0]), "+f"(d[1]), "+f"(d[2]), "+f"(d[3])
        : "r"(a[0]), "r"(a[1]), "r"(a[2]), "r"(a[3]), "r"(b[0]), "r"(b[1]));
}

// transposed 2x m8n8 b16 load (B-frag for row-major [k][n] tiles)
__device__ __forceinline__ void ldmx2t(uint32_t b[2], uint32_t saddr) {
    asm volatile("ldmatrix.sync.aligned.m8n8.x2.trans.shared.b16 {%0,%1}, [%2];"
        : "=r"(b[0]), "=r"(b[1]) : "r"(saddr));
}

// ---------------------------------------------------------------------------
// Positional encoding: fp32 angle (matches jax), cheap double range-reduce,
// fp32 sincos.
// ---------------------------------------------------------------------------
__global__ void pe_kernel() {
    int idx = blockIdx.x * blockDim.x + threadIdx.x;
    if (idx >= SLEN * (DMODEL/2)) return;
    int s = idx / (DMODEL/2);
    int i = idx % (DMODEL/2);
    float e = (2.0f * (float)i) / (float)DMODEL;
    double divd = exp2((double)e * 13.287712379549449);  // 10000^e
    float fdiv = (float)divd;
    float a = (float)s / fdiv;                            // fp32 like jax
    // range-reduce in double, evaluate in fp32
    double ad = (double)a;
    double k = rint(ad * 0.15915494309189535);
    float r = (float)(ad - k * 6.283185307179586);
    float sv, cv;
    sincosf(r, &sv, &cv);
    g_pe[s*DMODEL + 2*i]     = sv;
    g_pe[s*DMODEL + 2*i + 1] = cv;
}

// ---------------------------------------------------------------------------
// Split the 4 weight matrices into bf16 hi/lo
// ---------------------------------------------------------------------------
__global__ void wsplit_kernel(const float* __restrict__ wq, const float* __restrict__ wk,
                              const float* __restrict__ wv, const float* __restrict__ wo) {
    int idx = blockIdx.x * blockDim.x + threadIdx.x;   // 0..16383
    const float* Ws[4] = {wq, wk, wv, wo};
    #pragma unroll
    for (int m = 0; m < 4; m++) {
        __nv_bfloat16 h, l;
        split1(Ws[m][idx], h, l);
        g_wh[m * DMODEL * DMODEL + idx] = h;
        g_wl[m * DMODEL * DMODEL + idx] = l;
    }
}

// ---------------------------------------------------------------------------
// QKV projection via HMMA (outputs pre-split bf16 hi/lo; Q pre-scaled)
// ---------------------------------------------------------------------------
__global__ __launch_bounds__(128) void qkv_mma_kernel(
        const int* __restrict__ seq, const float* __restrict__ emb) {
    int tid = threadIdx.x;
    int w = tid >> 5, lane = tid & 31;
    int g = lane >> 2, u = lane & 3;
    int m0 = (blockIdx.x >> 1) * 64 + 16 * w;
    int jbase = (blockIdx.x & 1) * 8;

    int ra = m0 + g, rb = ra + 8;
    int tok_a = seq[ra], tok_b = seq[rb];
    int sa = ra & (SLEN - 1), sb = rb & (SLEN - 1);
    const float* Ea = emb + (long)tok_a * DMODEL;
    const float* Eb = emb + (long)tok_b * DMODEL;
    const float* Pa = g_pe + sa * DMODEL;
    const float* Pb = g_pe + sb * DMODEL;

    uint32_t xh[8][4], xl[8][4];
    #pragma unroll
    for (int ks = 0; ks < 8; ks++) {
        int c = 16 * ks + 2 * u;
        float2 e0, p0;
        e0 = *(const float2*)(Ea + c);     p0 = *(const float2*)(Pa + c);
        split2(e0.x + p0.x, e0.y + p0.y, xh[ks][0], xl[ks][0]);
        e0 = *(const float2*)(Eb + c);     p0 = *(const float2*)(Pb + c);
        split2(e0.x + p0.x, e0.y + p0.y, xh[ks][1], xl[ks][1]);
        e0 = *(const float2*)(Ea + c + 8); p0 = *(const float2*)(Pa + c + 8);
        split2(e0.x + p0.x, e0.y + p0.y, xh[ks][2], xl[ks][2]);
        e0 = *(const float2*)(Eb + c + 8); p0 = *(const float2*)(Pb + c + 8);
        split2(e0.x + p0.x, e0.y + p0.y, xh[ks][3], xl[ks][3]);
    }

    const float scale = 0.17677669529663687f;  // 1/sqrt(32)

    #pragma unroll
    for (int mat = 0; mat < 3; mat++) {
        const __nv_bfloat16* wh = g_wh + mat * DMODEL * DMODEL;
        const __nv_bfloat16* wl = g_wl + mat * DMODEL * DMODEL;
        __nv_bfloat16* oh = (mat == 0) ? g_qh : ((mat == 1) ? g_kh : g_vh);
        __nv_bfloat16* ol = (mat == 0) ? g_ql : ((mat == 1) ? g_kl : g_vl);

        float acc[8][4];
        #pragma unroll
        for (int j = 0; j < 8; j++)
            #pragma unroll
            for (int e = 0; e < 4; e++) acc[j][e] = 0.f;

        #pragma unroll
        for (int ks = 0; ks < 8; ks++) {
            #pragma unroll
            for (int j = 0; j < 8; j++) {
                int n = (jbase + j) * 8 + g;
                const uint32_t* bhp = (const uint32_t*)(wh + n * DMODEL + 16 * ks + 2 * u);
                const uint32_t* blp = (const uint32_t*)(wl + n * DMODEL + 16 * ks + 2 * u);
                uint32_t bh[2] = { bhp[0], bhp[4] };
                uint32_t bl[2] = { blp[0], blp[4] };
                mma_bf16(acc[j], xh[ks], bh);
                mma_bf16(acc[j], xl[ks], bh);
                mma_bf16(acc[j], xh[ks], bl);
            }
        }

        float sc = (mat == 0) ? scale : 1.0f;
        #pragma unroll
        for (int j = 0; j < 8; j++) {
            int cbase = (jbase + j) * 8 + 2 * u;
            uint32_t h0, l0;
            split2(acc[j][0] * sc, acc[j][1] * sc, h0, l0);
            *(uint32_t*)(oh + (long)ra * DMODEL + cbase) = h0;
            *(uint32_t*)(ol + (long)ra * DMODEL + cbase) = l0;
            split2(acc[j][2] * sc, acc[j][3] * sc, h0, l0);
            *(uint32_t*)(oh + (long)rb * DMODEL + cbase) = h0;
            *(uint32_t*)(ol + (long)rb * DMODEL + cbase) = l0;
        }
    }
}

// ---------------------------------------------------------------------------
// HMMA flash attention v2: 64-key halves (s[8][4] -> 2 CTAs/SM), V natural
// layout + ldmatrix.trans B-frags, diag half-skip.
// SMEM: K hi/lo + V hi/lo, all [128 keys][80B stride] (64B data + 16B pad).
// ---------------------------------------------------------------------------
#define KHOFF 0
#define KLOFF 10240
#define VHOFF 20480
#define VLOFF 30720
#define ATT_SMEM 40960

__global__ __launch_bounds__(256, 2) void attn_mma_kernel() {
    __shared__ char smem[ATT_SMEM];
    uint32_t sbase = smem_u32(smem);
    int tid = threadIdx.x;
    int w = tid >> 5, lane = tid & 31;
    int g = lane >> 2, u = lane & 3;

    int x = blockIdx.x;
    int qt = (x & 1) ? (x >> 1) : (31 - (x >> 1));   // snake balance
    int hb = blockIdx.y;
    long hoff = (long)hb * SLEN * HDIM;

    const __nv_bfloat16* Kbh = g_kh + hoff;
    const __nv_bfloat16* Kbl = g_kl + hoff;
    const __nv_bfloat16* Vbh = g_vh + hoff;
    const __nv_bfloat16* Vbl = g_vl + hoff;

    // ---- Q A-fragments (pre-scaled, pre-split) ----
    int r0 = qt * 128 + 16 * w + g;
    uint32_t qh[2][4], ql[2][4];
    {
        const __nv_bfloat16* Qbh = g_qh + hoff;
        const __nv_bfloat16* Qbl = g_ql + hoff;
        #pragma unroll
        for (int kt = 0; kt < 2; kt++) {
            int c = 16 * kt + 2 * u;
            qh[kt][0] = *(const uint32_t*)(Qbh + (long)r0 * HDIM + c);
            qh[kt][1] = *(const uint32_t*)(Qbh + (long)(r0 + 8) * HDIM + c);
            qh[kt][2] = *(const uint32_t*)(Qbh + (long)r0 * HDIM + c + 8);
            qh[kt][3] = *(const uint32_t*)(Qbh + (long)(r0 + 8) * HDIM + c + 8);
            ql[kt][0] = *(const uint32_t*)(Qbl + (long)r0 * HDIM + c);
            ql[kt][1] = *(const uint32_t*)(Qbl + (long)(r0 + 8) * HDIM + c);
            ql[kt][2] = *(const uint32_t*)(Qbl + (long)r0 * HDIM + c + 8);
            ql[kt][3] = *(const uint32_t*)(Qbl + (long)(r0 + 8) * HDIM + c + 8);
        }
    }

    float O[4][4];
    #pragma unroll
    for (int jo = 0; jo < 4; jo++)
        #pragma unroll
        for (int e = 0; e < 4; e++) O[jo][e] = 0.f;
    float lsum0 = 0.f, lsum1 = 0.f;

    for (int jt = 0; jt <= qt; jt++) {
        __syncthreads();
        long toff = (long)jt * 128 * HDIM;
        // ---- stage K and V (plain padded copies, per thread 8 uint4) ----
        #pragma unroll
        for (int it = 0; it < 2; it++) {
            int gi = tid + it * 256;             // 512 uint4 per buffer
            int key = gi >> 2, q4 = gi & 3;
            const long so = toff + key * HDIM + 8 * q4;
            int dofs = key * 80 + 16 * q4;
            *(uint4*)(smem + KHOFF + dofs) = *(const uint4*)(Kbh + so);
            *(uint4*)(smem + KLOFF + dofs) = *(const uint4*)(Kbl + so);
            *(uint4*)(smem + VHOFF + dofs) = *(const uint4*)(Vbh + so);
            *(uint4*)(smem + VLOFF + dofs) = *(const uint4*)(Vbl + so);
        }
        __syncthreads();

        bool diag = (jt == qt);
        int rloc0 = 16 * w + g;

        #pragma unroll
        for (int h = 0; h < 2; h++) {
            if (diag && h == 1 && w < 4) continue;   // fully masked half

            // ---- S = Q K^T over 64 keys ----
            float s[8][4];
            #pragma unroll
            for (int j = 0; j < 8; j++) {
                const char* kr = smem + (64 * h + 8 * j + g) * 80 + 4 * u;
                uint32_t bh0[2] = { *(const uint32_t*)(kr + KHOFF),      *(const uint32_t*)(kr + KHOFF + 16) };
                uint32_t bh1[2] = { *(const uint32_t*)(kr + KHOFF + 32), *(const uint32_t*)(kr + KHOFF + 48) };
                uint32_t bl0[2] = { *(const uint32_t*)(kr + KLOFF),      *(const uint32_t*)(kr + KLOFF + 16) };
                uint32_t bl1[2] = { *(const uint32_t*)(kr + KLOFF + 32), *(const uint32_t*)(kr + KLOFF + 48) };
                s[j][0] = 0.f; s[j][1] = 0.f; s[j][2] = 0.f; s[j][3] = 0.f;
                mma_bf16(s[j], qh[0], bh0);
                mma_bf16(s[j], qh[1], bh1);
                mma_bf16(s[j], qh[0], bl0);
                mma_bf16(s[j], qh[1], bl1);
                mma_bf16(s[j], ql[0], bh0);
                mma_bf16(s[j], ql[1], bh1);
            }

            // ---- softmax (no max subtraction; scores bounded) ----
            #pragma unroll
            for (int j = 0; j < 8; j++) {
                #pragma unroll
                for (int e = 0; e < 4; e++) {
                    float p = __expf(fabsf(s[j][e]));
                    if (diag) {
                        int col = 64 * h + 8 * j + 2 * u + (e & 1);
                        int row = rloc0 + ((e >= 2) ? 8 : 0);
                        if (col > row) p = 0.f;
                    }
                    s[j][e] = p;
                }
                lsum0 += s[j][0] + s[j][1];
                lsum1 += s[j][2] + s[j][3];
            }

            // ---- O += P V  (V B-frags via ldmatrix.trans) ----
            #pragma unroll
            for (int kt = 0; kt < 4; kt++) {
                uint32_t ah[4], al[4];
                split2(s[2*kt][0],   s[2*kt][1],   ah[0], al[0]);
                split2(s[2*kt][2],   s[2*kt][3],   ah[1], al[1]);
                split2(s[2*kt+1][0], s[2*kt+1][1], ah[2], al[2]);
                split2(s[2*kt+1][2], s[2*kt+1][3], ah[3], al[3]);
                uint32_t rowb = sbase + (64 * h + 16 * kt + (lane & 15)) * 80;
                #pragma unroll
                for (int jo = 0; jo < 4; jo++) {
                    uint32_t bh[2], bl[2];
                    ldmx2t(bh, rowb + VHOFF + 16 * jo);
                    ldmx2t(bl, rowb + VLOFF + 16 * jo);
                    mma_bf16(O[jo], ah, bh);
                    mma_bf16(O[jo], ah, bl);
                    mma_bf16(O[jo], al, bh);
                }
            }
        }
    }

    // ---- normalize + split-store O to bf16 hi/lo ----
    lsum0 += __shfl_xor_sync(0xffffffffu, lsum0, 1);
    lsum0 += __shfl_xor_sync(0xffffffffu, lsum0, 2);
    lsum1 += __shfl_xor_sync(0xffffffffu, lsum1, 1);
    lsum1 += __shfl_xor_sync(0xffffffffu, lsum1, 2);
    float inv0 = 1.0f / lsum0;
    float inv1 = 1.0f / lsum1;

    __nv_bfloat16* Oh = g_oh + hoff;
    __nv_bfloat16* Ol = g_ol + hoff;
    #pragma unroll
    for (int jo = 0; jo < 4; jo++) {
        int cbase = 8 * jo + 2 * u;
        uint32_t h0, l0;
        split2(O[jo][0] * inv0, O[jo][1] * inv0, h0, l0);
        *(uint32_t*)(Oh + (long)r0 * HDIM + cbase) = h0;
        *(uint32_t*)(Ol + (long)r0 * HDIM + cbase) = l0;
        split2(O[jo][2] * inv1, O[jo][3] * inv1, h0, l0);
        *(uint32_t*)(Oh + (long)(r0 + 8) * HDIM + cbase) = h0;
        *(uint32_t*)(Ol + (long)(r0 + 8) * HDIM + cbase) = l0;
    }
}

// ---------------------------------------------------------------------------
// Output projection via HMMA (register-resident)
// ---------------------------------------------------------------------------
__global__ __launch_bounds__(128) void oproj_mma_kernel(float* __restrict__ out) {
    int tid = threadIdx.x;
    int w = tid >> 5, lane = tid & 31;
    int g = lane >> 2, u = lane & 3;
    int m0 = (blockIdx.x >> 1) * 64 + 16 * w;
    int jbase = (blockIdx.x & 1) * 8;

    int ra = m0 + g, rb = ra + 8;

    uint32_t xh[8][4], xl[8][4];
    #pragma unroll
    for (int ks = 0; ks < 8; ks++) {
        int c = 16 * ks + 2 * u;
        xh[ks][0] = *(const uint32_t*)(g_oh + (long)ra * DMODEL + c);
        xh[ks][1] = *(const uint32_t*)(g_oh + (long)rb * DMODEL + c);
        xh[ks][2] = *(const uint32_t*)(g_oh + (long)ra * DMODEL + c + 8);
        xh[ks][3] = *(const uint32_t*)(g_oh + (long)rb * DMODEL + c + 8);
        xl[ks][0] = *(const uint32_t*)(g_ol + (long)ra * DMODEL + c);
        xl[ks][1] = *(const uint32_t*)(g_ol + (long)rb * DMODEL + c);
        xl[ks][2] = *(const uint32_t*)(g_ol + (long)ra * DMODEL + c + 8);
        xl[ks][3] = *(const uint32_t*)(g_ol + (long)rb * DMODEL + c + 8);
    }

    const __nv_bfloat16* wh = g_wh + 3 * DMODEL * DMODEL;
    const __nv_bfloat16* wl = g_wl + 3 * DMODEL * DMODEL;

    float acc[8][4];
    #pragma unroll
    for (int j = 0; j < 8; j++)
        #pragma unroll
        for (int e = 0; e < 4; e++) acc[j][e] = 0.f;

    #pragma unroll
    for (int ks = 0; ks < 8; ks++) {
        #pragma unroll
        for (int j = 0; j < 8; j++) {
            int n = (jbase + j) * 8 + g;
            const uint32_t* bhp = (const uint32_t*)(wh + n * DMODEL + 16 * ks + 2 * u);
            const uint32_t* blp = (const uint32_t*)(wl + n * DMODEL + 16 * ks + 2 * u);
            uint32_t bh[2] = { bhp[0], bhp[4] };
            uint32_t bl[2] = { blp[0], blp[4] };
            mma_bf16(acc[j], xh[ks], bh);
            mma_bf16(acc[j], xl[ks], bh);
            mma_bf16(acc[j], xh[ks], bl);
        }
    }

    #pragma unroll
    for (int j = 0; j < 8; j++) {
        int cbase = (jbase + j) * 8 + 2 * u;
        *(float2*)(out + (long)ra * DMODEL + cbase) = make_float2(acc[j][0], acc[j][1]);
        *(float2*)(out + (long)rb * DMODEL + cbase) = make_float2(acc[j][2], acc[j][3]);
    }
}

extern "C" void kernel_launch(void* const* d_in, const int* in_sizes, int n_in,
                              void* d_out, int out_size) {
    const int*   seq = (const int*)d_in[0];
    const float* emb = (const float*)d_in[1];
    const float* wq  = (const float*)d_in[2];
    const float* wk  = (const float*)d_in[3];
    const float* wv  = (const float*)d_in[4];
    const float* wo  = (const float*)d_in[5];
    float* out = (float*)d_out;

    pe_kernel<<<(SLEN*(DMODEL/2) + 255)/256, 256>>>();
    wsplit_kernel<<<(DMODEL*DMODEL + 255)/256, 256>>>(wq, wk, wv, wo);
    qkv_mma_kernel<<<256, 128>>>(seq, emb);
    attn_mma_kernel<<<dim3(32, NHB), 256>>>();
    oproj_mma_kernel<<<256, 128>>>(out);
}

// round 7
// speedup vs baseline: 3.9908x; 1.7813x over previous
#include <cuda_runtime.h>
#include <cuda_bf16.h>
#include <math.h>
#include <stdint.h>

#define BATCH 2
#define SLEN 4096
#define DMODEL 128
#define NHEAD 4
#define HDIM 32
#define NROW (BATCH*SLEN)   // 8192
#define NHB  (BATCH*NHEAD)  // 8

// Scratch (device globals — no allocation allowed)
__device__ float g_pe[SLEN*DMODEL];
__device__ __align__(16) __nv_bfloat16 g_qh[NROW*DMODEL], g_ql[NROW*DMODEL];
__device__ __align__(16) __nv_bfloat16 g_kh[NROW*DMODEL], g_kl[NROW*DMODEL];
__device__ __align__(16) __nv_bfloat16 g_vh[NROW*DMODEL], g_vl[NROW*DMODEL];
__device__ __align__(16) __nv_bfloat16 g_oh[NROW*DMODEL], g_ol[NROW*DMODEL];
// fragment-packed weights: [mat][n-octet(16)][kstep(8)][lane(32)] -> uint2 {b0,b1}
__device__ __align__(16) uint2 g_wph[4*4096], g_wpl[4*4096];
// partial attention outputs (unnormalized) + partial row sums, 2 slots
__device__ __align__(16) float g_po[2L*NHB*SLEN*HDIM];
__device__ float g_pl[2*NHB*SLEN];

// ---------------------------------------------------------------------------
// helpers
// ---------------------------------------------------------------------------
__device__ __forceinline__ uint32_t smem_u32(const void* p) {
    uint32_t a;
    asm("{ .reg .u64 t; cvta.to.shared.u64 t, %1; cvt.u32.u64 %0, t; }" : "=r"(a) : "l"(p));
    return a;
}

// pack two floats -> bf16x2 hi (e in low half, o in high) + bf16x2 residual
__device__ __forceinline__ void split2(float e, float o, uint32_t& hi, uint32_t& lo) {
    uint32_t h;
    asm("cvt.rn.bf16x2.f32 %0, %1, %2;" : "=r"(h) : "f"(o), "f"(e));
    float eh = __uint_as_float(h << 16);
    float oh = __uint_as_float(h & 0xffff0000u);
    float el = e - eh, ol = o - oh;
    uint32_t l;
    asm("cvt.rn.bf16x2.f32 %0, %1, %2;" : "=r"(l) : "f"(ol), "f"(el));
    hi = h; lo = l;
}

// D (in-place C) += A * B, m16n8k16 bf16 -> f32
__device__ __forceinline__ void mma_bf16(float d[4], const uint32_t a[4], const uint32_t b[2]) {
    asm volatile(
        "mma.sync.aligned.m16n8k16.row.col.f32.bf16.bf16.f32 "
        "{%0,%1,%2,%3},{%4,%5,%6,%7},{%8,%9},{%0,%1,%2,%3};"
        : "+f"(d[0]), "+f"(d[1]), "+f"(d[2]), "+f"(d[3])
        : "r"(a[0]), "r"(a[1]), "r"(a[2]), "r"(a[3]), "r"(b[0]), "r"(b[1]));
}

__device__ __forceinline__ void ldmx4(uint32_t d[4], uint32_t a) {
    asm volatile("ldmatrix.sync.aligned.m8n8.x4.shared.b16 {%0,%1,%2,%3}, [%4];"
        : "=r"(d[0]), "=r"(d[1]), "=r"(d[2]), "=r"(d[3]) : "r"(a));
}
__device__ __forceinline__ void ldmx4t(uint32_t d[4], uint32_t a) {
    asm volatile("ldmatrix.sync.aligned.m8n8.x4.trans.shared.b16 {%0,%1,%2,%3}, [%4];"
        : "=r"(d[0]), "=r"(d[1]), "=r"(d[2]), "=r"(d[3]) : "r"(a));
}

#define CP16(dst, src) asm volatile("cp.async.cg.shared.global [%0], [%1], 16;" :: "r"(dst), "l"(src) : "memory")
#define CP_COMMIT()    asm volatile("cp.async.commit_group;" ::: "memory")
#define CP_WAIT0()     asm volatile("cp.async.wait_group 0;" ::: "memory")

// ---------------------------------------------------------------------------
// Positional encoding
// ---------------------------------------------------------------------------
__global__ void pe_kernel() {
    int idx = blockIdx.x * blockDim.x + threadIdx.x;
    if (idx >= SLEN * (DMODEL/2)) return;
    int s = idx / (DMODEL/2);
    int i = idx % (DMODEL/2);
    float e = (2.0f * (float)i) / (float)DMODEL;
    double divd = exp2((double)e * 13.287712379549449);  // 10000^e
    float fdiv = (float)divd;
    float a = (float)s / fdiv;                            // fp32 like jax
    double ad = (double)a;
    double k = rint(ad * 0.15915494309189535);
    float r = (float)(ad - k * 6.283185307179586);
    float sv, cv;
    sincosf(r, &sv, &cv);
    g_pe[s*DMODEL + 2*i]     = sv;
    g_pe[s*DMODEL + 2*i + 1] = cv;
}

// ---------------------------------------------------------------------------
// Split weights into fragment-packed bf16 hi/lo:
// g_wph[mat][(no*8+ks)*32+lane] = {W[8no+g][16ks+2u..+1], W[8no+g][16ks+2u+8..+9]}
// ---------------------------------------------------------------------------
__global__ void wsplit_kernel(const float* __restrict__ wq, const float* __restrict__ wk,
                              const float* __restrict__ wv, const float* __restrict__ wo) {
    int idx = blockIdx.x * blockDim.x + threadIdx.x;   // 0..16383
    int mat = idx >> 12, rem = idx & 4095;
    int no = rem >> 8, ks = (rem >> 5) & 7, lane = rem & 31;
    int gg = lane >> 2, uu = lane & 3;
    const float* Ws[4] = {wq, wk, wv, wo};
    const float* W = Ws[mat];
    int n = 8 * no + gg, k0 = 16 * ks + 2 * uu;
    uint32_t h0, l0, h1, l1;
    split2(W[n*DMODEL + k0],     W[n*DMODEL + k0 + 1], h0, l0);
    split2(W[n*DMODEL + k0 + 8], W[n*DMODEL + k0 + 9], h1, l1);
    g_wph[idx] = make_uint2(h0, h1);
    g_wpl[idx] = make_uint2(l0, l1);
}

// ---------------------------------------------------------------------------
// QKV projection via HMMA, packed-W B-frags (coalesced LDG.64)
// ---------------------------------------------------------------------------
__global__ __launch_bounds__(128) void qkv_mma_kernel(
        const int* __restrict__ seq, const float* __restrict__ emb) {
    int tid = threadIdx.x;
    int w = tid >> 5, lane = tid & 31;
    int g = lane >> 2, u = lane & 3;
    int m0 = (blockIdx.x >> 1) * 64 + 16 * w;
    int jbase = (blockIdx.x & 1) * 8;

    int ra = m0 + g, rb = ra + 8;
    int tok_a = seq[ra], tok_b = seq[rb];
    int sa = ra & (SLEN - 1), sb = rb & (SLEN - 1);
    const float* Ea = emb + (long)tok_a * DMODEL;
    const float* Eb = emb + (long)tok_b * DMODEL;
    const float* Pa = g_pe + sa * DMODEL;
    const float* Pb = g_pe + sb * DMODEL;

    uint32_t xh[8][4], xl[8][4];
    #pragma unroll
    for (int ks = 0; ks < 8; ks++) {
        int c = 16 * ks + 2 * u;
        float2 e0, p0;
        e0 = *(const float2*)(Ea + c);     p0 = *(const float2*)(Pa + c);
        split2(e0.x + p0.x, e0.y + p0.y, xh[ks][0], xl[ks][0]);
        e0 = *(const float2*)(Eb + c);     p0 = *(const float2*)(Pb + c);
        split2(e0.x + p0.x, e0.y + p0.y, xh[ks][1], xl[ks][1]);
        e0 = *(const float2*)(Ea + c + 8); p0 = *(const float2*)(Pa + c + 8);
        split2(e0.x + p0.x, e0.y + p0.y, xh[ks][2], xl[ks][2]);
        e0 = *(const float2*)(Eb + c + 8); p0 = *(const float2*)(Pb + c + 8);
        split2(e0.x + p0.x, e0.y + p0.y, xh[ks][3], xl[ks][3]);
    }

    const float scale = 0.17677669529663687f;  // 1/sqrt(32)

    #pragma unroll
    for (int mat = 0; mat < 3; mat++) {
        const uint2* wph = g_wph + mat * 4096;
        const uint2* wpl = g_wpl + mat * 4096;
        __nv_bfloat16* oh = (mat == 0) ? g_qh : ((mat == 1) ? g_kh : g_vh);
        __nv_bfloat16* ol = (mat == 0) ? g_ql : ((mat == 1) ? g_kl : g_vl);

        float acc[8][4];
        #pragma unroll
        for (int j = 0; j < 8; j++)
            #pragma unroll
            for (int e = 0; e < 4; e++) acc[j][e] = 0.f;

        #pragma unroll
        for (int ks = 0; ks < 8; ks++) {
            #pragma unroll
            for (int j = 0; j < 8; j++) {
                int no = jbase + j;
                uint2 bhv = wph[(no * 8 + ks) * 32 + lane];
                uint2 blv = wpl[(no * 8 + ks) * 32 + lane];
                uint32_t bh[2] = { bhv.x, bhv.y };
                uint32_t bl[2] = { blv.x, blv.y };
                mma_bf16(acc[j], xh[ks], bh);
                mma_bf16(acc[j], xl[ks], bh);
                mma_bf16(acc[j], xh[ks], bl);
            }
        }

        float sc = (mat == 0) ? scale : 1.0f;
        #pragma unroll
        for (int j = 0; j < 8; j++) {
            int cbase = (jbase + j) * 8 + 2 * u;
            uint32_t h0, l0;
            split2(acc[j][0] * sc, acc[j][1] * sc, h0, l0);
            *(uint32_t*)(oh + (long)ra * DMODEL + cbase) = h0;
            *(uint32_t*)(ol + (long)ra * DMODEL + cbase) = l0;
            split2(acc[j][2] * sc, acc[j][3] * sc, h0, l0);
            *(uint32_t*)(oh + (long)rb * DMODEL + cbase) = h0;
            *(uint32_t*)(ol + (long)rb * DMODEL + cbase) = l0;
        }
    }
}

// ---------------------------------------------------------------------------
// HMMA flash attention v3: balanced work pairing + cp.async double buffering
// + ldmatrix.x4. Unnormalized partial O (fp32) + row sums to gmem; epilogue
// combines split tiles and normalizes.
//
// Pairing: unit u (0..15): q-tiles u and 31-u have u+1 + 32-u = 33 key tiles.
//   side0: q-tile u fully (u+1) + q-tile 31-u key-tiles [0,16-u)  -> 17 tiles
//   side1: q-tile 31-u key-tiles [16-u, 32-u) (incl diag)         -> 16 tiles
// SMEM: 2 x 40KB buffers of {KH,KL,VH,VL}, each [128 keys][80B stride].
// ---------------------------------------------------------------------------
#define KHOFF 0
#define KLOFF 10240
#define VHOFF 20480
#define VLOFF 30720
#define STAGE 40960

__device__ __forceinline__ void stage_tile(uint32_t sb,
        const char* kh, const char* kl, const char* vh, const char* vl,
        int jt, int tid) {
    long base = (long)jt * 128 * 64;   // 128 keys x 64 bytes
    #pragma unroll
    for (int it = 0; it < 2; it++) {
        int gi = tid + it * 256;
        int key = gi >> 2, q4 = gi & 3;
        int d = key * 80 + 16 * q4;
        long s = base + key * 64 + 16 * q4;
        CP16(sb + KHOFF + d, kh + s);
        CP16(sb + KLOFF + d, kl + s);
        CP16(sb + VHOFF + d, vh + s);
        CP16(sb + VLOFF + d, vl + s);
    }
}

__global__ __launch_bounds__(256, 2) void attn_mma_kernel() {
    extern __shared__ char smem[];
    uint32_t sbase = smem_u32(smem);
    int tid = threadIdx.x;
    int w = tid >> 5, lane = tid & 31;
    int g = lane >> 2, u = lane & 3;

    int x = blockIdx.x;
    int pu = x >> 1, side = x & 1;
    int hb = blockIdx.y;
    long hoff = (long)hb * SLEN * HDIM;

    const char* Kh = (const char*)(g_kh + hoff);
    const char* Kl = (const char*)(g_kl + hoff);
    const char* Vh = (const char*)(g_vh + hoff);
    const char* Vl = (const char*)(g_vl + hoff);
    const __nv_bfloat16* Qbh = g_qh + hoff;
    const __nv_bfloat16* Qbl = g_ql + hoff;
    float* PO = g_po + ((long)side * NHB + hb) * SLEN * HDIM;
    float* PL = g_pl + ((long)side * NHB + hb) * SLEN;

    int qts[2], j0s[2], j1s[2], nseg;
    if (side == 0) {
        qts[0] = pu;      j0s[0] = 0;       j1s[0] = pu + 1;
        qts[1] = 31 - pu; j0s[1] = 0;       j1s[1] = 16 - pu;
        nseg = 2;
    } else {
        qts[0] = 31 - pu; j0s[0] = 16 - pu; j1s[0] = 32 - pu;
        nseg = 1;
    }

    for (int sg = 0; sg < nseg; sg++) {
        int qt = qts[sg], j0 = j0s[sg], j1 = j1s[sg];
        __syncthreads();   // previous segment done with both buffers
        stage_tile(sbase, Kh, Kl, Vh, Vl, j0, tid);
        CP_COMMIT();

        // ---- Q A-fragments (pre-scaled, pre-split) ----
        int r0 = qt * 128 + 16 * w + g;
        uint32_t qh[2][4], ql[2][4];
        #pragma unroll
        for (int kt = 0; kt < 2; kt++) {
            int c = 16 * kt + 2 * u;
            qh[kt][0] = *(const uint32_t*)(Qbh + (long)r0 * HDIM + c);
            qh[kt][1] = *(const uint32_t*)(Qbh + (long)(r0 + 8) * HDIM + c);
            qh[kt][2] = *(const uint32_t*)(Qbh + (long)r0 * HDIM + c + 8);
            qh[kt][3] = *(const uint32_t*)(Qbh + (long)(r0 + 8) * HDIM + c + 8);
            ql[kt][0] = *(const uint32_t*)(Qbl + (long)r0 * HDIM + c);
            ql[kt][1] = *(const uint32_t*)(Qbl + (long)(r0 + 8) * HDIM + c);
            ql[kt][2] = *(const uint32_t*)(Qbl + (long)r0 * HDIM + c + 8);
            ql[kt][3] = *(const uint32_t*)(Qbl + (long)(r0 + 8) * HDIM + c + 8);
        }

        float O[4][4];
        #pragma unroll
        for (int jo = 0; jo < 4; jo++)
            #pragma unroll
            for (int e = 0; e < 4; e++) O[jo][e] = 0.f;
        float lsum0 = 0.f, lsum1 = 0.f;

        for (int jt = j0; jt < j1; jt++) {
            CP_WAIT0();
            __syncthreads();
            uint32_t sb = sbase + ((jt - j0) & 1) * STAGE;
            if (jt + 1 < j1) {
                stage_tile(sbase + ((jt + 1 - j0) & 1) * STAGE, Kh, Kl, Vh, Vl, jt + 1, tid);
                CP_COMMIT();
            }

            bool diag = (jt == qt);
            int rloc0 = 16 * w + g;

            #pragma unroll
            for (int h = 0; h < 2; h++) {
                if (diag && h == 1 && w < 4) continue;   // fully masked half

                // ---- S = Q K^T over 64 keys (ldmatrix.x4 K frags) ----
                float s[8][4];
                #pragma unroll
                for (int j = 0; j < 8; j++) {
                    uint32_t ka = sb + (64*h + 8*j + (lane & 7)) * 80 + 16 * (lane >> 3);
                    uint32_t bh4[4], bl4[4];
                    ldmx4(bh4, ka + KHOFF);
                    ldmx4(bl4, ka + KLOFF);
                    s[j][0] = 0.f; s[j][1] = 0.f; s[j][2] = 0.f; s[j][3] = 0.f;
                    mma_bf16(s[j], qh[0], &bh4[0]);
                    mma_bf16(s[j], qh[1], &bh4[2]);
                    mma_bf16(s[j], qh[0], &bl4[0]);
                    mma_bf16(s[j], qh[1], &bl4[2]);
                    mma_bf16(s[j], ql[0], &bh4[0]);
                    mma_bf16(s[j], ql[1], &bh4[2]);
                }

                // ---- softmax (no max subtraction; scores bounded) ----
                #pragma unroll
                for (int j = 0; j < 8; j++) {
                    #pragma unroll
                    for (int e = 0; e < 4; e++) {
                        float p = __expf(fabsf(s[j][e]));
                        if (diag) {
                            int col = 64*h + 8*j + 2*u + (e & 1);
                            int row = rloc0 + ((e >= 2) ? 8 : 0);
                            if (col > row) p = 0.f;
                        }
                        s[j][e] = p;
                    }
                    lsum0 += s[j][0] + s[j][1];
                    lsum1 += s[j][2] + s[j][3];
                }

                // ---- O += P V (ldmatrix.x4.trans V frags, 2 jo per load) ----
                #pragma unroll
                for (int kt = 0; kt < 4; kt++) {
                    uint32_t ah[4], al[4];
                    split2(s[2*kt][0],   s[2*kt][1],   ah[0], al[0]);
                    split2(s[2*kt][2],   s[2*kt][3],   ah[1], al[1]);
                    split2(s[2*kt+1][0], s[2*kt+1][1], ah[2], al[2]);
                    split2(s[2*kt+1][2], s[2*kt+1][3], ah[3], al[3]);
                    uint32_t rowb = sb + (64*h + 16*kt + (lane & 15)) * 80 + 16 * (lane >> 4);
                    #pragma unroll
                    for (int jop = 0; jop < 2; jop++) {
                        uint32_t vh4[4], vl4[4];
                        ldmx4t(vh4, rowb + VHOFF + 32 * jop);
                        ldmx4t(vl4, rowb + VLOFF + 32 * jop);
                        mma_bf16(O[2*jop],   ah, &vh4[0]);
                        mma_bf16(O[2*jop],   ah, &vl4[0]);
                        mma_bf16(O[2*jop],   al, &vh4[0]);
                        mma_bf16(O[2*jop+1], ah, &vh4[2]);
                        mma_bf16(O[2*jop+1], ah, &vl4[2]);
                        mma_bf16(O[2*jop+1], al, &vh4[2]);
                    }
                }
            }
        }

        // ---- store unnormalized partial O + partial row sums ----
        #pragma unroll
        for (int jo = 0; jo < 4; jo++) {
            int cb = 8 * jo + 2 * u;
            *(float2*)(PO + (long)r0 * HDIM + cb)       = make_float2(O[jo][0], O[jo][1]);
            *(float2*)(PO + (long)(r0 + 8) * HDIM + cb) = make_float2(O[jo][2], O[jo][3]);
        }
        lsum0 += __shfl_xor_sync(0xffffffffu, lsum0, 1);
        lsum0 += __shfl_xor_sync(0xffffffffu, lsum0, 2);
        lsum1 += __shfl_xor_sync(0xffffffffu, lsum1, 1);
        lsum1 += __shfl_xor_sync(0xffffffffu, lsum1, 2);
        if (u == 0) {
            PL[r0]     = lsum0;
            PL[r0 + 8] = lsum1;
        }
    }
}

// ---------------------------------------------------------------------------
// Epilogue: combine split partials, normalize, split-store O to bf16 hi/lo.
// q-tiles 0..15 live only in slot0; 16..31 are slot0+slot1.
// ---------------------------------------------------------------------------
__global__ __launch_bounds__(256) void attn_epilogue_kernel() {
    int idx = blockIdx.x * blockDim.x + threadIdx.x;   // 262144
    int hb_row = idx >> 3;
    int q4 = idx & 7;
    int row = hb_row & (SLEN - 1);
    int qt = row >> 7;

    float l = g_pl[hb_row];
    float4 o = *((const float4*)g_po + (long)hb_row * 8 + q4);
    if (qt >= 16) {
        l += g_pl[NHB * SLEN + hb_row];
        float4 o1 = *((const float4*)(g_po + (long)NHB * SLEN * HDIM) + (long)hb_row * 8 + q4);
        o.x += o1.x; o.y += o1.y; o.z += o1.z; o.w += o1.w;
    }
    float inv = 1.0f / l;
    uint32_t h0, l0, h1, l1;
    split2(o.x * inv, o.y * inv, h0, l0);
    split2(o.z * inv, o.w * inv, h1, l1);
    *(uint2*)(g_oh + (long)hb_row * HDIM + 4 * q4) = make_uint2(h0, h1);
    *(uint2*)(g_ol + (long)hb_row * HDIM + 4 * q4) = make_uint2(l0, l1);
}

// ---------------------------------------------------------------------------
// Output projection via HMMA (packed-W B-frags)
// ---------------------------------------------------------------------------
__global__ __launch_bounds__(128) void oproj_mma_kernel(float* __restrict__ out) {
    int tid = threadIdx.x;
    int w = tid >> 5, lane = tid & 31;
    int g = lane >> 2, u = lane & 3;
    int m0 = (blockIdx.x >> 1) * 64 + 16 * w;
    int jbase = (blockIdx.x & 1) * 8;

    int ra = m0 + g, rb = ra + 8;

    uint32_t xh[8][4], xl[8][4];
    #pragma unroll
    for (int ks = 0; ks < 8; ks++) {
        int c = 16 * ks + 2 * u;
        xh[ks][0] = *(const uint32_t*)(g_oh + (long)ra * DMODEL + c);
        xh[ks][1] = *(const uint32_t*)(g_oh + (long)rb * DMODEL + c);
        xh[ks][2] = *(const uint32_t*)(g_oh + (long)ra * DMODEL + c + 8);
        xh[ks][3] = *(const uint32_t*)(g_oh + (long)rb * DMODEL + c + 8);
        xl[ks][0] = *(const uint32_t*)(g_ol + (long)ra * DMODEL + c);
        xl[ks][1] = *(const uint32_t*)(g_ol + (long)rb * DMODEL + c);
        xl[ks][2] = *(const uint32_t*)(g_ol + (long)ra * DMODEL + c + 8);
        xl[ks][3] = *(const uint32_t*)(g_ol + (long)rb * DMODEL + c + 8);
    }

    const uint2* wph = g_wph + 3 * 4096;
    const uint2* wpl = g_wpl + 3 * 4096;

    float acc[8][4];
    #pragma unroll
    for (int j = 0; j < 8; j++)
        #pragma unroll
        for (int e = 0; e < 4; e++) acc[j][e] = 0.f;

    #pragma unroll
    for (int ks = 0; ks < 8; ks++) {
        #pragma unroll
        for (int j = 0; j < 8; j++) {
            int no = jbase + j;
            uint2 bhv = wph[(no * 8 + ks) * 32 + lane];
            uint2 blv = wpl[(no * 8 + ks) * 32 + lane];
            uint32_t bh[2] = { bhv.x, bhv.y };
            uint32_t bl[2] = { blv.x, blv.y };
            mma_bf16(acc[j], xh[ks], bh);
            mma_bf16(acc[j], xl[ks], bh);
            mma_bf16(acc[j], xh[ks], bl);
        }
    }

    #pragma unroll
    for (int j = 0; j < 8; j++) {
        int cbase = (jbase + j) * 8 + 2 * u;
        *(float2*)(out + (long)ra * DMODEL + cbase) = make_float2(acc[j][0], acc[j][1]);
        *(float2*)(out + (long)rb * DMODEL + cbase) = make_float2(acc[j][2], acc[j][3]);
    }
}

extern "C" void kernel_launch(void* const* d_in, const int* in_sizes, int n_in,
                              void* d_out, int out_size) {
    const int*   seq = (const int*)d_in[0];
    const float* emb = (const float*)d_in[1];
    const float* wq  = (const float*)d_in[2];
    const float* wk  = (const float*)d_in[3];
    const float* wv  = (const float*)d_in[4];
    const float* wo  = (const float*)d_in[5];
    float* out = (float*)d_out;

    cudaFuncSetAttribute(attn_mma_kernel,
                         cudaFuncAttributeMaxDynamicSharedMemorySize, 2 * STAGE);

    pe_kernel<<<(SLEN*(DMODEL/2) + 255)/256, 256>>>();
    wsplit_kernel<<<64, 256>>>(wq, wk, wv, wo);
    qkv_mma_kernel<<<256, 128>>>(seq, emb);
    attn_mma_kernel<<<dim3(32, NHB), 256, 2 * STAGE>>>();
    attn_epilogue_kernel<<<1024, 256>>>();
    oproj_mma_kernel<<<256, 128>>>(out);
}

// round 9
// speedup vs baseline: 4.8413x; 1.2131x over previous
#include <cuda_runtime.h>
#include <cuda_fp16.h>
#include <math.h>
#include <stdint.h>

#define BATCH 2
#define SLEN 4096
#define DMODEL 128
#define NHEAD 4
#define HDIM 32
#define NROW (BATCH*SLEN)   // 8192
#define NHB  (BATCH*NHEAD)  // 8

// Scratch (device globals — no allocation allowed)
__device__ float g_pe[SLEN*DMODEL];
__device__ __align__(16) __half g_qh[NROW*DMODEL], g_ql[NROW*DMODEL];
__device__ __align__(16) __half g_kh[NROW*DMODEL], g_kl[NROW*DMODEL];
__device__ __align__(16) __half g_vh[NROW*DMODEL];
// fragment-packed weights: [mat][n-octet(16)][kstep(8)][lane(32)] -> uint2 {b0,b1}
__device__ __align__(16) uint2 g_wph[4*4096], g_wpl[4*4096];
// partial attention outputs (unnormalized fp32) + partial row sums, 2 slots
__device__ __align__(16) float g_po[2L*NHB*SLEN*HDIM];
__device__ float g_pl[2*NHB*SLEN];

// ---------------------------------------------------------------------------
// helpers
// ---------------------------------------------------------------------------
__device__ __forceinline__ uint32_t smem_u32(const void* p) {
    uint32_t a;
    asm("{ .reg .u64 t; cvta.to.shared.u64 t, %1; cvt.u32.u64 %0, t; }" : "=r"(a) : "l"(p));
    return a;
}

// pack two floats -> f16x2 hi (e in low half, o in high) + f16x2 residual
__device__ __forceinline__ void split2h(float e, float o, uint32_t& hi, uint32_t& lo) {
    uint32_t h;
    asm("cvt.rn.f16x2.f32 %0, %1, %2;" : "=r"(h) : "f"(o), "f"(e));
    float2 f = __half22float2(*(__half2*)&h);
    uint32_t l;
    asm("cvt.rn.f16x2.f32 %0, %1, %2;" : "=r"(l) : "f"(o - f.y), "f"(e - f.x));
    hi = h; lo = l;
}
// hi-only pack
__device__ __forceinline__ uint32_t pack2h(float e, float o) {
    uint32_t h;
    asm("cvt.rn.f16x2.f32 %0, %1, %2;" : "=r"(h) : "f"(o), "f"(e));
    return h;
}

// D (in-place C) += A * B, m16n8k16 fp16 -> f32
__device__ __forceinline__ void mma_f16(float d[4], const uint32_t a[4], const uint32_t b[2]) {
    asm volatile(
        "mma.sync.aligned.m16n8k16.row.col.f32.f16.f16.f32 "
        "{%0,%1,%2,%3},{%4,%5,%6,%7},{%8,%9},{%0,%1,%2,%3};"
        : "+f"(d[0]), "+f"(d[1]), "+f"(d[2]), "+f"(d[3])
        : "r"(a[0]), "r"(a[1]), "r"(a[2]), "r"(a[3]), "r"(b[0]), "r"(b[1]));
}

__device__ __forceinline__ void ldmx4(uint32_t d[4], uint32_t a) {
    asm volatile("ldmatrix.sync.aligned.m8n8.x4.shared.b16 {%0,%1,%2,%3}, [%4];"
        : "=r"(d[0]), "=r"(d[1]), "=r"(d[2]), "=r"(d[3]) : "r"(a));
}
__device__ __forceinline__ void ldmx4t(uint32_t d[4], uint32_t a) {
    asm volatile("ldmatrix.sync.aligned.m8n8.x4.trans.shared.b16 {%0,%1,%2,%3}, [%4];"
        : "=r"(d[0]), "=r"(d[1]), "=r"(d[2]), "=r"(d[3]) : "r"(a));
}

#define CP16(dst, src) asm volatile("cp.async.cg.shared.global [%0], [%1], 16;" :: "r"(dst), "l"(src) : "memory")
#define CP_COMMIT()    asm volatile("cp.async.commit_group;" ::: "memory")
#define CP_WAIT0()     asm volatile("cp.async.wait_group 0;" ::: "memory")

// ---------------------------------------------------------------------------
// Prep: positional encoding (blocks >= 64) + weight split/pack (blocks < 64)
// ---------------------------------------------------------------------------
__global__ void prep_kernel(const float* __restrict__ wq, const float* __restrict__ wk,
                            const float* __restrict__ wv, const float* __restrict__ wo) {
    int bid = blockIdx.x;
    if (bid < 64) {
        int idx = bid * 256 + threadIdx.x;      // 0..16383
        int mat = idx >> 12, rem = idx & 4095;
        int no = rem >> 8, ks = (rem >> 5) & 7, lane = rem & 31;
        int gg = lane >> 2, uu = lane & 3;
        const float* Ws[4] = {wq, wk, wv, wo};
        const float* W = Ws[mat];
        int n = 8 * no + gg, k0 = 16 * ks + 2 * uu;
        uint32_t h0, l0, h1, l1;
        split2h(W[n*DMODEL + k0],     W[n*DMODEL + k0 + 1], h0, l0);
        split2h(W[n*DMODEL + k0 + 8], W[n*DMODEL + k0 + 9], h1, l1);
        g_wph[idx] = make_uint2(h0, h1);
        g_wpl[idx] = make_uint2(l0, l1);
    } else {
        int idx = (bid - 64) * 256 + threadIdx.x;
        if (idx >= SLEN * (DMODEL/2)) return;
        int s = idx / (DMODEL/2);
        int i = idx % (DMODEL/2);
        float e = (2.0f * (float)i) / (float)DMODEL;
        double divd = exp2((double)e * 13.287712379549449);  // 10000^e
        float fdiv = (float)divd;
        float a = (float)s / fdiv;                            // fp32 like jax
        double ad = (double)a;
        double k = rint(ad * 0.15915494309189535);
        float r = (float)(ad - k * 6.283185307179586);
        float sv, cv;
        sincosf(r, &sv, &cv);
        g_pe[s*DMODEL + 2*i]     = sv;
        g_pe[s*DMODEL + 2*i + 1] = cv;
    }
}

// ---------------------------------------------------------------------------
// QKV projection via HMMA (fp16, 3-term). Outputs: q scaled by log2e/sqrt(32)
// hi/lo, k hi/lo, v hi only.
// ---------------------------------------------------------------------------
__global__ __launch_bounds__(128) void qkv_mma_kernel(
        const int* __restrict__ seq, const float* __restrict__ emb) {
    int tid = threadIdx.x;
    int w = tid >> 5, lane = tid & 31;
    int g = lane >> 2, u = lane & 3;
    int m0 = (blockIdx.x >> 1) * 64 + 16 * w;
    int jbase = (blockIdx.x & 1) * 8;

    int ra = m0 + g, rb = ra + 8;
    int tok_a = seq[ra], tok_b = seq[rb];
    int sa = ra & (SLEN - 1), sb = rb & (SLEN - 1);
    const float* Ea = emb + (long)tok_a * DMODEL;
    const float* Eb = emb + (long)tok_b * DMODEL;
    const float* Pa = g_pe + sa * DMODEL;
    const float* Pb = g_pe + sb * DMODEL;

    uint32_t xh[8][4], xl[8][4];
    #pragma unroll
    for (int ks = 0; ks < 8; ks++) {
        int c = 16 * ks + 2 * u;
        float2 e0, p0;
        e0 = *(const float2*)(Ea + c);     p0 = *(const float2*)(Pa + c);
        split2h(e0.x + p0.x, e0.y + p0.y, xh[ks][0], xl[ks][0]);
        e0 = *(const float2*)(Eb + c);     p0 = *(const float2*)(Pb + c);
        split2h(e0.x + p0.x, e0.y + p0.y, xh[ks][1], xl[ks][1]);
        e0 = *(const float2*)(Ea + c + 8); p0 = *(const float2*)(Pa + c + 8);
        split2h(e0.x + p0.x, e0.y + p0.y, xh[ks][2], xl[ks][2]);
        e0 = *(const float2*)(Eb + c + 8); p0 = *(const float2*)(Pb + c + 8);
        split2h(e0.x + p0.x, e0.y + p0.y, xh[ks][3], xl[ks][3]);
    }

    // 1/sqrt(32) * log2(e): folds softmax's exp->exp2 conversion into Q
    const float qscale = 0.17677669529663687f * 1.4426950408889634f;

    #pragma unroll
    for (int mat = 0; mat < 3; mat++) {
        const uint2* wph = g_wph + mat * 4096;
        const uint2* wpl = g_wpl + mat * 4096;

        float acc[8][4];
        #pragma unroll
        for (int j = 0; j < 8; j++)
            #pragma unroll
            for (int e = 0; e < 4; e++) acc[j][e] = 0.f;

        #pragma unroll
        for (int ks = 0; ks < 8; ks++) {
            #pragma unroll
            for (int j = 0; j < 8; j++) {
                int no = jbase + j;
                uint2 bhv = wph[(no * 8 + ks) * 32 + lane];
                uint2 blv = wpl[(no * 8 + ks) * 32 + lane];
                uint32_t bh[2] = { bhv.x, bhv.y };
                uint32_t bl[2] = { blv.x, blv.y };
                mma_f16(acc[j], xh[ks], bh);
                mma_f16(acc[j], xl[ks], bh);
                mma_f16(acc[j], xh[ks], bl);
            }
        }

        #pragma unroll
        for (int j = 0; j < 8; j++) {
            int cbase = (jbase + j) * 8 + 2 * u;
            if (mat == 0) {
                uint32_t h0, l0;
                split2h(acc[j][0] * qscale, acc[j][1] * qscale, h0, l0);
                *(uint32_t*)(g_qh + (long)ra * DMODEL + cbase) = h0;
                *(uint32_t*)(g_ql + (long)ra * DMODEL + cbase) = l0;
                split2h(acc[j][2] * qscale, acc[j][3] * qscale, h0, l0);
                *(uint32_t*)(g_qh + (long)rb * DMODEL + cbase) = h0;
                *(uint32_t*)(g_ql + (long)rb * DMODEL + cbase) = l0;
            } else if (mat == 1) {
                uint32_t h0, l0;
                split2h(acc[j][0], acc[j][1], h0, l0);
                *(uint32_t*)(g_kh + (long)ra * DMODEL + cbase) = h0;
                *(uint32_t*)(g_kl + (long)ra * DMODEL + cbase) = l0;
                split2h(acc[j][2], acc[j][3], h0, l0);
                *(uint32_t*)(g_kh + (long)rb * DMODEL + cbase) = h0;
                *(uint32_t*)(g_kl + (long)rb * DMODEL + cbase) = l0;
            } else {
                *(uint32_t*)(g_vh + (long)ra * DMODEL + cbase) = pack2h(acc[j][0], acc[j][1]);
                *(uint32_t*)(g_vh + (long)rb * DMODEL + cbase) = pack2h(acc[j][2], acc[j][3]);
            }
        }
    }
}

// ---------------------------------------------------------------------------
// HMMA flash attention v4: fp16, 3-term S / 2-term PV (split P x V-hi),
// exponent-shifted exp2 softmax (p' = 2^(|s'|-5); shift cancels in O/L),
// balanced pairing + cp.async double buffering + ldmatrix.x4.
// SMEM per stage: KH,KL,VH each [128 keys][80B stride] = 30KB; 2 stages.
// ---------------------------------------------------------------------------
#define KHOFF 0
#define KLOFF 10240
#define VHOFF 20480
#define STAGE 30720
#define PSHIFT 5.0f

__device__ __forceinline__ void stage_tile(uint32_t sb,
        const char* kh, const char* kl, const char* vh, int jt, int tid) {
    long base = (long)jt * 128 * 64;   // 128 keys x 64 bytes
    #pragma unroll
    for (int it = 0; it < 2; it++) {
        int gi = tid + it * 256;
        int key = gi >> 2, q4 = gi & 3;
        int d = key * 80 + 16 * q4;
        long s = base + key * 64 + 16 * q4;
        CP16(sb + KHOFF + d, kh + s);
        CP16(sb + KLOFF + d, kl + s);
        CP16(sb + VHOFF + d, vh + s);
    }
}

__global__ __launch_bounds__(256, 2) void attn_mma_kernel() {
    extern __shared__ char smem[];
    uint32_t sbase = smem_u32(smem);
    int tid = threadIdx.x;
    int w = tid >> 5, lane = tid & 31;
    int g = lane >> 2, u = lane & 3;

    int x = blockIdx.x;
    int pu = x >> 1, side = x & 1;
    int hb = blockIdx.y;
    long hoff = (long)hb * SLEN * HDIM;

    const char* Kh = (const char*)(g_kh + hoff);
    const char* Kl = (const char*)(g_kl + hoff);
    const char* Vh = (const char*)(g_vh + hoff);
    const __half* Qbh = g_qh + hoff;
    const __half* Qbl = g_ql + hoff;
    float* PO = g_po + ((long)side * NHB + hb) * SLEN * HDIM;
    float* PL = g_pl + ((long)side * NHB + hb) * SLEN;

    int qts[2], j0s[2], j1s[2], nseg;
    if (side == 0) {
        qts[0] = pu;      j0s[0] = 0;       j1s[0] = pu + 1;
        qts[1] = 31 - pu; j0s[1] = 0;       j1s[1] = 16 - pu;
        nseg = 2;
    } else {
        qts[0] = 31 - pu; j0s[0] = 16 - pu; j1s[0] = 32 - pu;
        nseg = 1;
    }

    for (int sg = 0; sg < nseg; sg++) {
        int qt = qts[sg], j0 = j0s[sg], j1 = j1s[sg];
        __syncthreads();   // previous segment done with both buffers
        stage_tile(sbase, Kh, Kl, Vh, j0, tid);
        CP_COMMIT();

        // ---- Q A-fragments (pre-scaled by log2e/sqrt(32), pre-split) ----
        int r0 = qt * 128 + 16 * w + g;
        uint32_t qh[2][4], ql[2][4];
        #pragma unroll
        for (int kt = 0; kt < 2; kt++) {
            int c = 16 * kt + 2 * u;
            qh[kt][0] = *(const uint32_t*)(Qbh + (long)r0 * HDIM + c);
            qh[kt][1] = *(const uint32_t*)(Qbh + (long)(r0 + 8) * HDIM + c);
            qh[kt][2] = *(const uint32_t*)(Qbh + (long)r0 * HDIM + c + 8);
            qh[kt][3] = *(const uint32_t*)(Qbh + (long)(r0 + 8) * HDIM + c + 8);
            ql[kt][0] = *(const uint32_t*)(Qbl + (long)r0 * HDIM + c);
            ql[kt][1] = *(const uint32_t*)(Qbl + (long)(r0 + 8) * HDIM + c);
            ql[kt][2] = *(const uint32_t*)(Qbl + (long)r0 * HDIM + c + 8);
            ql[kt][3] = *(const uint32_t*)(Qbl + (long)(r0 + 8) * HDIM + c + 8);
        }

        float O[4][4];
        #pragma unroll
        for (int jo = 0; jo < 4; jo++)
            #pragma unroll
            for (int e = 0; e < 4; e++) O[jo][e] = 0.f;
        float lsum0 = 0.f, lsum1 = 0.f;

        for (int jt = j0; jt < j1; jt++) {
            CP_WAIT0();
            __syncthreads();
            uint32_t sb = sbase + ((jt - j0) & 1) * STAGE;
            if (jt + 1 < j1) {
                stage_tile(sbase + ((jt + 1 - j0) & 1) * STAGE, Kh, Kl, Vh, jt + 1, tid);
                CP_COMMIT();
            }

            bool diag = (jt == qt);
            int rloc0 = 16 * w + g;

            #pragma unroll
            for (int h = 0; h < 2; h++) {
                if (diag && h == 1 && w < 4) continue;   // fully masked half

                // ---- S = Q K^T over 64 keys (ldmatrix.x4 K frags) ----
                float s[8][4];
                #pragma unroll
                for (int j = 0; j < 8; j++) {
                    uint32_t ka = sb + (64*h + 8*j + (lane & 7)) * 80 + 16 * (lane >> 3);
                    uint32_t bh4[4], bl4[4];
                    ldmx4(bh4, ka + KHOFF);
                    ldmx4(bl4, ka + KLOFF);
                    s[j][0] = 0.f; s[j][1] = 0.f; s[j][2] = 0.f; s[j][3] = 0.f;
                    mma_f16(s[j], qh[0], &bh4[0]);
                    mma_f16(s[j], qh[1], &bh4[2]);
                    mma_f16(s[j], qh[0], &bl4[0]);
                    mma_f16(s[j], qh[1], &bl4[2]);
                    mma_f16(s[j], ql[0], &bh4[0]);
                    mma_f16(s[j], ql[1], &bh4[2]);
                }

                // ---- softmax: p' = 2^(|s'| - PSHIFT); shift cancels in O/L --
                #pragma unroll
                for (int j = 0; j < 8; j++) {
                    #pragma unroll
                    for (int e = 0; e < 4; e++) {
                        float p = exp2f(fabsf(s[j][e]) - PSHIFT);
                        if (diag) {
                            int col = 64*h + 8*j + 2*u + (e & 1);
                            int row = rloc0 + ((e >= 2) ? 8 : 0);
                            if (col > row) p = 0.f;
                        }
                        s[j][e] = p;
                    }
                    lsum0 += s[j][0] + s[j][1];
                    lsum1 += s[j][2] + s[j][3];
                }

                // ---- O += P V (split P hi/lo x V-hi; ldmatrix.x4.trans) ----
                #pragma unroll
                for (int kt = 0; kt < 4; kt++) {
                    uint32_t ah[4], al[4];
                    split2h(s[2*kt][0],   s[2*kt][1],   ah[0], al[0]);
                    split2h(s[2*kt][2],   s[2*kt][3],   ah[1], al[1]);
                    split2h(s[2*kt+1][0], s[2*kt+1][1], ah[2], al[2]);
                    split2h(s[2*kt+1][2], s[2*kt+1][3], ah[3], al[3]);
                    uint32_t rowb = sb + (64*h + 16*kt + (lane & 15)) * 80 + 16 * (lane >> 4);
                    #pragma unroll
                    for (int jop = 0; jop < 2; jop++) {
                        uint32_t vh4[4];
                        ldmx4t(vh4, rowb + VHOFF + 32 * jop);
                        mma_f16(O[2*jop],   ah, &vh4[0]);
                        mma_f16(O[2*jop],   al, &vh4[0]);
                        mma_f16(O[2*jop+1], ah, &vh4[2]);
                        mma_f16(O[2*jop+1], al, &vh4[2]);
                    }
                }
            }
        }

        // ---- store unnormalized partial O + partial row sums ----
        #pragma unroll
        for (int jo = 0; jo < 4; jo++) {
            int cb = 8 * jo + 2 * u;
            *(float2*)(PO + (long)r0 * HDIM + cb)       = make_float2(O[jo][0], O[jo][1]);
            *(float2*)(PO + (long)(r0 + 8) * HDIM + cb) = make_float2(O[jo][2], O[jo][3]);
        }
        lsum0 += __shfl_xor_sync(0xffffffffu, lsum0, 1);
        lsum0 += __shfl_xor_sync(0xffffffffu, lsum0, 2);
        lsum1 += __shfl_xor_sync(0xffffffffu, lsum1, 1);
        lsum1 += __shfl_xor_sync(0xffffffffu, lsum1, 2);
        if (u == 0) {
            PL[r0]     = lsum0;
            PL[r0 + 8] = lsum1;
        }
    }
}

// ---------------------------------------------------------------------------
// Output projection with fused attention epilogue.
// Plain-view mapping: X row ra (within-batch row sa) belongs ENTIRELY to head
// h' = sa>>10; column c is seq position (sa&1023)*4 + (c>>5), dim c&31.
// For kstep ks: pos offset p = ks>>1, dim base = (ks&1)*16 + 2u (+8).
// ---------------------------------------------------------------------------
__global__ __launch_bounds__(128) void oproj_mma_kernel(float* __restrict__ out) {
    int tid = threadIdx.x;
    int w = tid >> 5, lane = tid & 31;
    int g = lane >> 2, u = lane & 3;
    int m0 = (blockIdx.x >> 1) * 64 + 16 * w;
    int jbase = (blockIdx.x & 1) * 8;

    int ra = m0 + g, rb = ra + 8;
    int ba = ra >> 12, sa = ra & (SLEN - 1);
    int bb = rb >> 12, sb = rb & (SLEN - 1);
    int ha = sa >> 10, hb2 = sb >> 10;                 // head index (fixed per row)
    int pa0 = (sa & 1023) * 4, pb0 = (sb & 1023) * 4;  // base seq position
    bool two_a = (sa & 1023) >= 512;
    bool two_b = (sb & 1023) >= 512;
    const float* PO1 = g_po + (long)NHB * SLEN * HDIM;
    const float* PL1 = g_pl + NHB * SLEN;

    // normalizers: one per pos offset (0..3)
    float inva[4], invb[4];
    #pragma unroll
    for (int p = 0; p < 4; p++) {
        long ia = ((long)(ba * 4 + ha)) * SLEN + pa0 + p;
        float la = g_pl[ia] + (two_a ? PL1[ia] : 0.f);
        inva[p] = 1.0f / la;
        long ib = ((long)(bb * 4 + hb2)) * SLEN + pb0 + p;
        float lb = g_pl[ib] + (two_b ? PL1[ib] : 0.f);
        invb[p] = 1.0f / lb;
    }

    uint32_t xh[8][4], xl[8][4];
    #pragma unroll
    for (int ks = 0; ks < 8; ks++) {
        int p = ks >> 1;
        int d0 = (ks & 1) * 16 + 2 * u;
        long base_a = (((long)(ba * 4 + ha)) * SLEN + pa0 + p) * HDIM;
        float2 a0 = *(const float2*)(g_po + base_a + d0);
        float2 a1 = *(const float2*)(g_po + base_a + d0 + 8);
        if (two_a) {
            float2 q0 = *(const float2*)(PO1 + base_a + d0);
            float2 q1 = *(const float2*)(PO1 + base_a + d0 + 8);
            a0.x += q0.x; a0.y += q0.y; a1.x += q1.x; a1.y += q1.y;
        }
        split2h(a0.x * inva[p], a0.y * inva[p], xh[ks][0], xl[ks][0]);
        split2h(a1.x * inva[p], a1.y * inva[p], xh[ks][2], xl[ks][2]);

        long base_b = (((long)(bb * 4 + hb2)) * SLEN + pb0 + p) * HDIM;
        float2 b0 = *(const float2*)(g_po + base_b + d0);
        float2 b1 = *(const float2*)(g_po + base_b + d0 + 8);
        if (two_b) {
            float2 q0 = *(const float2*)(PO1 + base_b + d0);
            float2 q1 = *(const float2*)(PO1 + base_b + d0 + 8);
            b0.x += q0.x; b0.y += q0.y; b1.x += q1.x; b1.y += q1.y;
        }
        split2h(b0.x * invb[p], b0.y * invb[p], xh[ks][1], xl[ks][1]);
        split2h(b1.x * invb[p], b1.y * invb[p], xh[ks][3], xl[ks][3]);
    }

    const uint2* wph = g_wph + 3 * 4096;
    const uint2* wpl = g_wpl + 3 * 4096;

    float acc[8][4];
    #pragma unroll
    for (int j = 0; j < 8; j++)
        #pragma unroll
        for (int e = 0; e < 4; e++) acc[j][e] = 0.f;

    #pragma unroll
    for (int ks = 0; ks < 8; ks++) {
        #pragma unroll
        for (int j = 0; j < 8; j++) {
            int no = jbase + j;
            uint2 bhv = wph[(no * 8 + ks) * 32 + lane];
            uint2 blv = wpl[(no * 8 + ks) * 32 + lane];
            uint32_t bh[2] = { bhv.x, bhv.y };
            uint32_t bl[2] = { blv.x, blv.y };
            mma_f16(acc[j], xh[ks], bh);
            mma_f16(acc[j], xl[ks], bh);
            mma_f16(acc[j], xh[ks], bl);
        }
    }

    #pragma unroll
    for (int j = 0; j < 8; j++) {
        int cbase = (jbase + j) * 8 + 2 * u;
        *(float2*)(out + (long)ra * DMODEL + cbase) = make_float2(acc[j][0], acc[j][1]);
        *(float2*)(out + (long)rb * DMODEL + cbase) = make_float2(acc[j][2], acc[j][3]);
    }
}

extern "C" void kernel_launch(void* const* d_in, const int* in_sizes, int n_in,
                              void* d_out, int out_size) {
    const int*   seq = (const int*)d_in[0];
    const float* emb = (const float*)d_in[1];
    const float* wq  = (const float*)d_in[2];
    const float* wk  = (const float*)d_in[3];
    const float* wv  = (const float*)d_in[4];
    const float* wo  = (const float*)d_in[5];
    float* out = (float*)d_out;

    cudaFuncSetAttribute(attn_mma_kernel,
                         cudaFuncAttributeMaxDynamicSharedMemorySize, 2 * STAGE);

    prep_kernel<<<64 + (SLEN*(DMODEL/2) + 255)/256, 256>>>(wq, wk, wv, wo);
    qkv_mma_kernel<<<256, 128>>>(seq, emb);
    attn_mma_kernel<<<dim3(32, NHB), 256, 2 * STAGE>>>();
    oproj_mma_kernel<<<256, 128>>>(out);
}

// round 10
// speedup vs baseline: 5.5157x; 1.1393x over previous
#include <cuda_runtime.h>
#include <cuda_fp16.h>
#include <math.h>
#include <stdint.h>

#define BATCH 2
#define SLEN 4096
#define DMODEL 128
#define NHEAD 4
#define HDIM 32
#define NROW (BATCH*SLEN)   // 8192
#define NHB  (BATCH*NHEAD)  // 8

// Scratch (device globals — no allocation allowed)
__device__ float g_pe[SLEN*DMODEL];
__device__ __align__(16) __half g_qh[NROW*DMODEL], g_ql[NROW*DMODEL];
__device__ __align__(16) __half g_kh[NROW*DMODEL], g_kl[NROW*DMODEL];
__device__ __align__(16) __half g_vh[NROW*DMODEL];
// fragment-packed weights: [mat][n-octet(16)][kstep(8)][lane(32)] -> uint2 {b0,b1}
__device__ __align__(16) uint2 g_wph[4*4096], g_wpl[4*4096];
// partial attention outputs (unnormalized fp32) + partial row sums, 2 slots
__device__ __align__(16) float g_po[2L*NHB*SLEN*HDIM];
__device__ float g_pl[2*NHB*SLEN];

// ---------------------------------------------------------------------------
// helpers
// ---------------------------------------------------------------------------
__device__ __forceinline__ uint32_t smem_u32(const void* p) {
    uint32_t a;
    asm("{ .reg .u64 t; cvta.to.shared.u64 t, %1; cvt.u32.u64 %0, t; }" : "=r"(a) : "l"(p));
    return a;
}

// pack two floats -> f16x2 hi (e in low half, o in high) + f16x2 residual
__device__ __forceinline__ void split2h(float e, float o, uint32_t& hi, uint32_t& lo) {
    uint32_t h;
    asm("cvt.rn.f16x2.f32 %0, %1, %2;" : "=r"(h) : "f"(o), "f"(e));
    float2 f = __half22float2(*(__half2*)&h);
    uint32_t l;
    asm("cvt.rn.f16x2.f32 %0, %1, %2;" : "=r"(l) : "f"(o - f.y), "f"(e - f.x));
    hi = h; lo = l;
}
// hi-only pack
__device__ __forceinline__ uint32_t pack2h(float e, float o) {
    uint32_t h;
    asm("cvt.rn.f16x2.f32 %0, %1, %2;" : "=r"(h) : "f"(o), "f"(e));
    return h;
}
// guaranteed single-MUFU exp2
__device__ __forceinline__ float ex2(float x) {
    float r;
    asm("ex2.approx.f32 %0, %1;" : "=f"(r) : "f"(x));
    return r;
}

// D (in-place C) += A * B, m16n8k16 fp16 -> f32
__device__ __forceinline__ void mma_f16(float d[4], const uint32_t a[4], const uint32_t b[2]) {
    asm volatile(
        "mma.sync.aligned.m16n8k16.row.col.f32.f16.f16.f32 "
        "{%0,%1,%2,%3},{%4,%5,%6,%7},{%8,%9},{%0,%1,%2,%3};"
        : "+f"(d[0]), "+f"(d[1]), "+f"(d[2]), "+f"(d[3])
        : "r"(a[0]), "r"(a[1]), "r"(a[2]), "r"(a[3]), "r"(b[0]), "r"(b[1]));
}

__device__ __forceinline__ void ldmx4(uint32_t d[4], uint32_t a) {
    asm volatile("ldmatrix.sync.aligned.m8n8.x4.shared.b16 {%0,%1,%2,%3}, [%4];"
        : "=r"(d[0]), "=r"(d[1]), "=r"(d[2]), "=r"(d[3]) : "r"(a));
}
__device__ __forceinline__ void ldmx4t(uint32_t d[4], uint32_t a) {
    asm volatile("ldmatrix.sync.aligned.m8n8.x4.trans.shared.b16 {%0,%1,%2,%3}, [%4];"
        : "=r"(d[0]), "=r"(d[1]), "=r"(d[2]), "=r"(d[3]) : "r"(a));
}

#define CP16(dst, src) asm volatile("cp.async.cg.shared.global [%0], [%1], 16;" :: "r"(dst), "l"(src) : "memory")
#define CP_COMMIT()    asm volatile("cp.async.commit_group;" ::: "memory")
#define CP_WAIT0()     asm volatile("cp.async.wait_group 0;" ::: "memory")

// ---------------------------------------------------------------------------
// Prep: positional encoding (blocks >= 64) + weight split/pack (blocks < 64)
// ---------------------------------------------------------------------------
__global__ void prep_kernel(const float* __restrict__ wq, const float* __restrict__ wk,
                            const float* __restrict__ wv, const float* __restrict__ wo) {
    int bid = blockIdx.x;
    if (bid < 64) {
        int idx = bid * 256 + threadIdx.x;      // 0..16383
        int mat = idx >> 12, rem = idx & 4095;
        int no = rem >> 8, ks = (rem >> 5) & 7, lane = rem & 31;
        int gg = lane >> 2, uu = lane & 3;
        const float* Ws[4] = {wq, wk, wv, wo};
        const float* W = Ws[mat];
        int n = 8 * no + gg, k0 = 16 * ks + 2 * uu;
        uint32_t h0, l0, h1, l1;
        split2h(W[n*DMODEL + k0],     W[n*DMODEL + k0 + 1], h0, l0);
        split2h(W[n*DMODEL + k0 + 8], W[n*DMODEL + k0 + 9], h1, l1);
        g_wph[idx] = make_uint2(h0, h1);
        g_wpl[idx] = make_uint2(l0, l1);
    } else {
        int idx = (bid - 64) * 256 + threadIdx.x;
        if (idx >= SLEN * (DMODEL/2)) return;
        int s = idx / (DMODEL/2);
        int i = idx % (DMODEL/2);
        float e = (2.0f * (float)i) / (float)DMODEL;
        double divd = exp2((double)e * 13.287712379549449);  // 10000^e
        float fdiv = (float)divd;
        float a = (float)s / fdiv;                            // fp32 like jax
        double ad = (double)a;
        double k = rint(ad * 0.15915494309189535);
        float r = (float)(ad - k * 6.283185307179586);
        float sv, cv;
        sincosf(r, &sv, &cv);
        g_pe[s*DMODEL + 2*i]     = sv;
        g_pe[s*DMODEL + 2*i + 1] = cv;
    }
}

// ---------------------------------------------------------------------------
// QKV projection via HMMA (fp16, 3-term). Outputs: q scaled by log2e/sqrt(32)
// hi/lo, k hi/lo, v hi only.
// ---------------------------------------------------------------------------
__global__ __launch_bounds__(128) void qkv_mma_kernel(
        const int* __restrict__ seq, const float* __restrict__ emb) {
    int tid = threadIdx.x;
    int w = tid >> 5, lane = tid & 31;
    int g = lane >> 2, u = lane & 3;
    int m0 = (blockIdx.x >> 1) * 64 + 16 * w;
    int jbase = (blockIdx.x & 1) * 8;

    int ra = m0 + g, rb = ra + 8;
    int tok_a = seq[ra], tok_b = seq[rb];
    int sa = ra & (SLEN - 1), sb = rb & (SLEN - 1);
    const float* Ea = emb + (long)tok_a * DMODEL;
    const float* Eb = emb + (long)tok_b * DMODEL;
    const float* Pa = g_pe + sa * DMODEL;
    const float* Pb = g_pe + sb * DMODEL;

    uint32_t xh[8][4], xl[8][4];
    #pragma unroll
    for (int ks = 0; ks < 8; ks++) {
        int c = 16 * ks + 2 * u;
        float2 e0, p0;
        e0 = *(const float2*)(Ea + c);     p0 = *(const float2*)(Pa + c);
        split2h(e0.x + p0.x, e0.y + p0.y, xh[ks][0], xl[ks][0]);
        e0 = *(const float2*)(Eb + c);     p0 = *(const float2*)(Pb + c);
        split2h(e0.x + p0.x, e0.y + p0.y, xh[ks][1], xl[ks][1]);
        e0 = *(const float2*)(Ea + c + 8); p0 = *(const float2*)(Pa + c + 8);
        split2h(e0.x + p0.x, e0.y + p0.y, xh[ks][2], xl[ks][2]);
        e0 = *(const float2*)(Eb + c + 8); p0 = *(const float2*)(Pb + c + 8);
        split2h(e0.x + p0.x, e0.y + p0.y, xh[ks][3], xl[ks][3]);
    }

    // 1/sqrt(32) * log2(e): folds softmax's exp->exp2 conversion into Q
    const float qscale = 0.17677669529663687f * 1.4426950408889634f;

    #pragma unroll
    for (int mat = 0; mat < 3; mat++) {
        const uint2* wph = g_wph + mat * 4096;
        const uint2* wpl = g_wpl + mat * 4096;

        float acc[8][4];
        #pragma unroll
        for (int j = 0; j < 8; j++)
            #pragma unroll
            for (int e = 0; e < 4; e++) acc[j][e] = 0.f;

        #pragma unroll
        for (int ks = 0; ks < 8; ks++) {
            #pragma unroll
            for (int j = 0; j < 8; j++) {
                int no = jbase + j;
                uint2 bhv = wph[(no * 8 + ks) * 32 + lane];
                uint2 blv = wpl[(no * 8 + ks) * 32 + lane];
                uint32_t bh[2] = { bhv.x, bhv.y };
                uint32_t bl[2] = { blv.x, blv.y };
                mma_f16(acc[j], xh[ks], bh);
                mma_f16(acc[j], xl[ks], bh);
                mma_f16(acc[j], xh[ks], bl);
            }
        }

        #pragma unroll
        for (int j = 0; j < 8; j++) {
            int cbase = (jbase + j) * 8 + 2 * u;
            if (mat == 0) {
                uint32_t h0, l0;
                split2h(acc[j][0] * qscale, acc[j][1] * qscale, h0, l0);
                *(uint32_t*)(g_qh + (long)ra * DMODEL + cbase) = h0;
                *(uint32_t*)(g_ql + (long)ra * DMODEL + cbase) = l0;
                split2h(acc[j][2] * qscale, acc[j][3] * qscale, h0, l0);
                *(uint32_t*)(g_qh + (long)rb * DMODEL + cbase) = h0;
                *(uint32_t*)(g_ql + (long)rb * DMODEL + cbase) = l0;
            } else if (mat == 1) {
                uint32_t h0, l0;
                split2h(acc[j][0], acc[j][1], h0, l0);
                *(uint32_t*)(g_kh + (long)ra * DMODEL + cbase) = h0;
                *(uint32_t*)(g_kl + (long)ra * DMODEL + cbase) = l0;
                split2h(acc[j][2], acc[j][3], h0, l0);
                *(uint32_t*)(g_kh + (long)rb * DMODEL + cbase) = h0;
                *(uint32_t*)(g_kl + (long)rb * DMODEL + cbase) = l0;
            } else {
                *(uint32_t*)(g_vh + (long)ra * DMODEL + cbase) = pack2h(acc[j][0], acc[j][1]);
                *(uint32_t*)(g_vh + (long)rb * DMODEL + cbase) = pack2h(acc[j][2], acc[j][3]);
            }
        }
    }
}

// ---------------------------------------------------------------------------
// HMMA flash attention v5: fp16, 3-term S / 1-term PV (P-hi x V-hi),
// exponent-shifted MUFU exp2 (p' = 2^(|s'|-5); shift cancels in O/L),
// balanced pairing + cp.async double buffering + ldmatrix.x4.
// SMEM per stage: KH,KL,VH each [128 keys][80B stride] = 30KB; 2 stages.
// ---------------------------------------------------------------------------
#define KHOFF 0
#define KLOFF 10240
#define VHOFF 20480
#define STAGE 30720
#define PSHIFT 5.0f

__device__ __forceinline__ void stage_tile(uint32_t sb,
        const char* kh, const char* kl, const char* vh, int jt, int tid) {
    long base = (long)jt * 128 * 64;   // 128 keys x 64 bytes
    #pragma unroll
    for (int it = 0; it < 2; it++) {
        int gi = tid + it * 256;
        int key = gi >> 2, q4 = gi & 3;
        int d = key * 80 + 16 * q4;
        long s = base + key * 64 + 16 * q4;
        CP16(sb + KHOFF + d, kh + s);
        CP16(sb + KLOFF + d, kl + s);
        CP16(sb + VHOFF + d, vh + s);
    }
}

__global__ __launch_bounds__(256, 2) void attn_mma_kernel() {
    extern __shared__ char smem[];
    uint32_t sbase = smem_u32(smem);
    int tid = threadIdx.x;
    int w = tid >> 5, lane = tid & 31;
    int g = lane >> 2, u = lane & 3;

    int x = blockIdx.x;
    int pu = x >> 1, side = x & 1;
    int hb = blockIdx.y;
    long hoff = (long)hb * SLEN * HDIM;

    const char* Kh = (const char*)(g_kh + hoff);
    const char* Kl = (const char*)(g_kl + hoff);
    const char* Vh = (const char*)(g_vh + hoff);
    const __half* Qbh = g_qh + hoff;
    const __half* Qbl = g_ql + hoff;
    float* PO = g_po + ((long)side * NHB + hb) * SLEN * HDIM;
    float* PL = g_pl + ((long)side * NHB + hb) * SLEN;

    int qts[2], j0s[2], j1s[2], nseg;
    if (side == 0) {
        qts[0] = pu;      j0s[0] = 0;       j1s[0] = pu + 1;
        qts[1] = 31 - pu; j0s[1] = 0;       j1s[1] = 16 - pu;
        nseg = 2;
    } else {
        qts[0] = 31 - pu; j0s[0] = 16 - pu; j1s[0] = 32 - pu;
        nseg = 1;
    }

    for (int sg = 0; sg < nseg; sg++) {
        int qt = qts[sg], j0 = j0s[sg], j1 = j1s[sg];
        __syncthreads();   // previous segment done with both buffers
        stage_tile(sbase, Kh, Kl, Vh, j0, tid);
        CP_COMMIT();

        // ---- Q A-fragments (pre-scaled by log2e/sqrt(32), pre-split) ----
        int r0 = qt * 128 + 16 * w + g;
        uint32_t qh[2][4], ql[2][4];
        #pragma unroll
        for (int kt = 0; kt < 2; kt++) {
            int c = 16 * kt + 2 * u;
            qh[kt][0] = *(const uint32_t*)(Qbh + (long)r0 * HDIM + c);
            qh[kt][1] = *(const uint32_t*)(Qbh + (long)(r0 + 8) * HDIM + c);
            qh[kt][2] = *(const uint32_t*)(Qbh + (long)r0 * HDIM + c + 8);
            qh[kt][3] = *(const uint32_t*)(Qbh + (long)(r0 + 8) * HDIM + c + 8);
            ql[kt][0] = *(const uint32_t*)(Qbl + (long)r0 * HDIM + c);
            ql[kt][1] = *(const uint32_t*)(Qbl + (long)(r0 + 8) * HDIM + c);
            ql[kt][2] = *(const uint32_t*)(Qbl + (long)r0 * HDIM + c + 8);
            ql[kt][3] = *(const uint32_t*)(Qbl + (long)(r0 + 8) * HDIM + c + 8);
        }

        float O[4][4];
        #pragma unroll
        for (int jo = 0; jo < 4; jo++)
            #pragma unroll
            for (int e = 0; e < 4; e++) O[jo][e] = 0.f;
        float lsum0 = 0.f, lsum1 = 0.f;

        for (int jt = j0; jt < j1; jt++) {
            CP_WAIT0();
            __syncthreads();
            uint32_t sb = sbase + ((jt - j0) & 1) * STAGE;
            if (jt + 1 < j1) {
                stage_tile(sbase + ((jt + 1 - j0) & 1) * STAGE, Kh, Kl, Vh, jt + 1, tid);
                CP_COMMIT();
            }

            bool diag = (jt == qt);
            int rloc0 = 16 * w + g;

            #pragma unroll
            for (int h = 0; h < 2; h++) {
                if (diag && h == 1 && w < 4) continue;   // fully masked half

                // ---- S = Q K^T over 64 keys (ldmatrix.x4 K frags) ----
                float s[8][4];
                #pragma unroll
                for (int j = 0; j < 8; j++) {
                    uint32_t ka = sb + (64*h + 8*j + (lane & 7)) * 80 + 16 * (lane >> 3);
                    uint32_t bh4[4], bl4[4];
                    ldmx4(bh4, ka + KHOFF);
                    ldmx4(bl4, ka + KLOFF);
                    s[j][0] = 0.f; s[j][1] = 0.f; s[j][2] = 0.f; s[j][3] = 0.f;
                    mma_f16(s[j], qh[0], &bh4[0]);
                    mma_f16(s[j], qh[1], &bh4[2]);
                    mma_f16(s[j], qh[0], &bl4[0]);
                    mma_f16(s[j], qh[1], &bl4[2]);
                    mma_f16(s[j], ql[0], &bh4[0]);
                    mma_f16(s[j], ql[1], &bh4[2]);
                }

                // ---- softmax: p' = 2^(|s'| - PSHIFT); shift cancels in O/L --
                #pragma unroll
                for (int j = 0; j < 8; j++) {
                    #pragma unroll
                    for (int e = 0; e < 4; e++) {
                        float p = ex2(fabsf(s[j][e]) - PSHIFT);
                        if (diag) {
                            int col = 64*h + 8*j + 2*u + (e & 1);
                            int row = rloc0 + ((e >= 2) ? 8 : 0);
                            if (col > row) p = 0.f;
                        }
                        s[j][e] = p;
                    }
                    lsum0 += s[j][0] + s[j][1];
                    lsum1 += s[j][2] + s[j][3];
                }

                // ---- O += P V (P-hi only x V-hi; ldmatrix.x4.trans) ----
                #pragma unroll
                for (int kt = 0; kt < 4; kt++) {
                    uint32_t ah[4];
                    ah[0] = pack2h(s[2*kt][0],   s[2*kt][1]);
                    ah[1] = pack2h(s[2*kt][2],   s[2*kt][3]);
                    ah[2] = pack2h(s[2*kt+1][0], s[2*kt+1][1]);
                    ah[3] = pack2h(s[2*kt+1][2], s[2*kt+1][3]);
                    uint32_t rowb = sb + (64*h + 16*kt + (lane & 15)) * 80 + 16 * (lane >> 4);
                    #pragma unroll
                    for (int jop = 0; jop < 2; jop++) {
                        uint32_t vh4[4];
                        ldmx4t(vh4, rowb + VHOFF + 32 * jop);
                        mma_f16(O[2*jop],   ah, &vh4[0]);
                        mma_f16(O[2*jop+1], ah, &vh4[2]);
                    }
                }
            }
        }

        // ---- store unnormalized partial O + partial row sums ----
        #pragma unroll
        for (int jo = 0; jo < 4; jo++) {
            int cb = 8 * jo + 2 * u;
            *(float2*)(PO + (long)r0 * HDIM + cb)       = make_float2(O[jo][0], O[jo][1]);
            *(float2*)(PO + (long)(r0 + 8) * HDIM + cb) = make_float2(O[jo][2], O[jo][3]);
        }
        lsum0 += __shfl_xor_sync(0xffffffffu, lsum0, 1);
        lsum0 += __shfl_xor_sync(0xffffffffu, lsum0, 2);
        lsum1 += __shfl_xor_sync(0xffffffffu, lsum1, 1);
        lsum1 += __shfl_xor_sync(0xffffffffu, lsum1, 2);
        if (u == 0) {
            PL[r0]     = lsum0;
            PL[r0 + 8] = lsum1;
        }
    }
}

// ---------------------------------------------------------------------------
// Output projection with fused attention epilogue.
// Plain-view mapping: X row ra (within-batch row sa) belongs ENTIRELY to head
// h' = sa>>10; column c is seq position (sa&1023)*4 + (c>>5), dim c&31.
// For kstep ks: pos offset p = ks>>1, dim base = (ks&1)*16 + 2u (+8).
// ---------------------------------------------------------------------------
__global__ __launch_bounds__(128) void oproj_mma_kernel(float* __restrict__ out) {
    int tid = threadIdx.x;
    int w = tid >> 5, lane = tid & 31;
    int g = lane >> 2, u = lane & 3;
    int m0 = (blockIdx.x >> 1) * 64 + 16 * w;
    int jbase = (blockIdx.x & 1) * 8;

    int ra = m0 + g, rb = ra + 8;
    int ba = ra >> 12, sa = ra & (SLEN - 1);
    int bb = rb >> 12, sb = rb & (SLEN - 1);
    int ha = sa >> 10, hb2 = sb >> 10;                 // head index (fixed per row)
    int pa0 = (sa & 1023) * 4, pb0 = (sb & 1023) * 4;  // base seq position
    bool two_a = (sa & 1023) >= 512;
    bool two_b = (sb & 1023) >= 512;
    const float* PO1 = g_po + (long)NHB * SLEN * HDIM;
    const float* PL1 = g_pl + NHB * SLEN;

    // normalizers: one per pos offset (0..3)
    float inva[4], invb[4];
    #pragma unroll
    for (int p = 0; p < 4; p++) {
        long ia = ((long)(ba * 4 + ha)) * SLEN + pa0 + p;
        float la = g_pl[ia] + (two_a ? PL1[ia] : 0.f);
        inva[p] = 1.0f / la;
        long ib = ((long)(bb * 4 + hb2)) * SLEN + pb0 + p;
        float lb = g_pl[ib] + (two_b ? PL1[ib] : 0.f);
        invb[p] = 1.0f / lb;
    }

    uint32_t xh[8][4], xl[8][4];
    #pragma unroll
    for (int ks = 0; ks < 8; ks++) {
        int p = ks >> 1;
        int d0 = (ks & 1) * 16 + 2 * u;
        long base_a = (((long)(ba * 4 + ha)) * SLEN + pa0 + p) * HDIM;
        float2 a0 = *(const float2*)(g_po + base_a + d0);
        float2 a1 = *(const float2*)(g_po + base_a + d0 + 8);
        if (two_a) {
            float2 q0 = *(const float2*)(PO1 + base_a + d0);
            float2 q1 = *(const float2*)(PO1 + base_a + d0 + 8);
            a0.x += q0.x; a0.y += q0.y; a1.x += q1.x; a1.y += q1.y;
        }
        split2h(a0.x * inva[p], a0.y * inva[p], xh[ks][0], xl[ks][0]);
        split2h(a1.x * inva[p], a1.y * inva[p], xh[ks][2], xl[ks][2]);

        long base_b = (((long)(bb * 4 + hb2)) * SLEN + pb0 + p) * HDIM;
        float2 b0 = *(const float2*)(g_po + base_b + d0);
        float2 b1 = *(const float2*)(g_po + base_b + d0 + 8);
        if (two_b) {
            float2 q0 = *(const float2*)(PO1 + base_b + d0);
            float2 q1 = *(const float2*)(PO1 + base_b + d0 + 8);
            b0.x += q0.x; b0.y += q0.y; b1.x += q1.x; b1.y += q1.y;
        }
        split2h(b0.x * invb[p], b0.y * invb[p], xh[ks][1], xl[ks][1]);
        split2h(b1.x * invb[p], b1.y * invb[p], xh[ks][3], xl[ks][3]);
    }

    const uint2* wph = g_wph + 3 * 4096;
    const uint2* wpl = g_wpl + 3 * 4096;

    float acc[8][4];
    #pragma unroll
    for (int j = 0; j < 8; j++)
        #pragma unroll
        for (int e = 0; e < 4; e++) acc[j][e] = 0.f;

    #pragma unroll
    for (int ks = 0; ks < 8; ks++) {
        #pragma unroll
        for (int j = 0; j < 8; j++) {
            int no = jbase + j;
            uint2 bhv = wph[(no * 8 + ks) * 32 + lane];
            uint2 blv = wpl[(no * 8 + ks) * 32 + lane];
            uint32_t bh[2] = { bhv.x, bhv.y };
            uint32_t bl[2] = { blv.x, blv.y };
            mma_f16(acc[j], xh[ks], bh);
            mma_f16(acc[j], xl[ks], bh);
            mma_f16(acc[j], xh[ks], bl);
        }
    }

    #pragma unroll
    for (int j = 0; j < 8; j++) {
        int cbase = (jbase + j) * 8 + 2 * u;
        *(float2*)(out + (long)ra * DMODEL + cbase) = make_float2(acc[j][0], acc[j][1]);
        *(float2*)(out + (long)rb * DMODEL + cbase) = make_float2(acc[j][2], acc[j][3]);
    }
}

extern "C" void kernel_launch(void* const* d_in, const int* in_sizes, int n_in,
                              void* d_out, int out_size) {
    const int*   seq = (const int*)d_in[0];
    const float* emb = (const float*)d_in[1];
    const float* wq  = (const float*)d_in[2];
    const float* wk  = (const float*)d_in[3];
    const float* wv  = (const float*)d_in[4];
    const float* wo  = (const float*)d_in[5];
    float* out = (float*)d_out;

    cudaFuncSetAttribute(attn_mma_kernel,
                         cudaFuncAttributeMaxDynamicSharedMemorySize, 2 * STAGE);

    prep_kernel<<<64 + (SLEN*(DMODEL/2) + 255)/256, 256>>>(wq, wk, wv, wo);
    qkv_mma_kernel<<<256, 128>>>(seq, emb);
    attn_mma_kernel<<<dim3(32, NHB), 256, 2 * STAGE>>>();
    oproj_mma_kernel<<<256, 128>>>(out);
}

// round 11
// speedup vs baseline: 5.6425x; 1.0230x over previous
#include <cuda_runtime.h>
#include <cuda_fp16.h>
#include <math.h>
#include <stdint.h>

#define BATCH 2
#define SLEN 4096
#define DMODEL 128
#define NHEAD 4
#define HDIM 32
#define NROW (BATCH*SLEN)   // 8192
#define NHB  (BATCH*NHEAD)  // 8

// Scratch (device globals — no allocation allowed)
__device__ float g_pe[SLEN*DMODEL];
__device__ __align__(16) __half g_qh[NROW*DMODEL], g_ql[NROW*DMODEL];
__device__ __align__(16) __half g_kh[NROW*DMODEL], g_kl[NROW*DMODEL];
__device__ __align__(16) __half g_vh[NROW*DMODEL];
// fragment-packed weights: [mat][n-octet(16)][kstep(8)][lane(32)] -> uint2 {b0,b1}
__device__ __align__(16) uint2 g_wph[4*4096], g_wpl[4*4096];
// partial attention outputs (unnormalized fp32) + partial row sums, 2 slots
__device__ __align__(16) float g_po[2L*NHB*SLEN*HDIM];
__device__ float g_pl[2*NHB*SLEN];

// ---------------------------------------------------------------------------
// helpers
// ---------------------------------------------------------------------------
__device__ __forceinline__ uint32_t smem_u32(const void* p) {
    uint32_t a;
    asm("{ .reg .u64 t; cvta.to.shared.u64 t, %1; cvt.u32.u64 %0, t; }" : "=r"(a) : "l"(p));
    return a;
}

// pack two floats -> f16x2 hi (e in low half, o in high) + f16x2 residual
__device__ __forceinline__ void split2h(float e, float o, uint32_t& hi, uint32_t& lo) {
    uint32_t h;
    asm("cvt.rn.f16x2.f32 %0, %1, %2;" : "=r"(h) : "f"(o), "f"(e));
    float2 f = __half22float2(*(__half2*)&h);
    uint32_t l;
    asm("cvt.rn.f16x2.f32 %0, %1, %2;" : "=r"(l) : "f"(o - f.y), "f"(e - f.x));
    hi = h; lo = l;
}
// hi-only pack
__device__ __forceinline__ uint32_t pack2h(float e, float o) {
    uint32_t h;
    asm("cvt.rn.f16x2.f32 %0, %1, %2;" : "=r"(h) : "f"(o), "f"(e));
    return h;
}
// guaranteed single-MUFU exp2
__device__ __forceinline__ float ex2(float x) {
    float r;
    asm("ex2.approx.f32 %0, %1;" : "=f"(r) : "f"(x));
    return r;
}

// D (in-place C) += A * B, m16n8k16 fp16 -> f32
__device__ __forceinline__ void mma_f16(float d[4], const uint32_t a[4], const uint32_t b[2]) {
    asm volatile(
        "mma.sync.aligned.m16n8k16.row.col.f32.f16.f16.f32 "
        "{%0,%1,%2,%3},{%4,%5,%6,%7},{%8,%9},{%0,%1,%2,%3};"
        : "+f"(d[0]), "+f"(d[1]), "+f"(d[2]), "+f"(d[3])
        : "r"(a[0]), "r"(a[1]), "r"(a[2]), "r"(a[3]), "r"(b[0]), "r"(b[1]));
}

__device__ __forceinline__ void ldmx4(uint32_t d[4], uint32_t a) {
    asm volatile("ldmatrix.sync.aligned.m8n8.x4.shared.b16 {%0,%1,%2,%3}, [%4];"
        : "=r"(d[0]), "=r"(d[1]), "=r"(d[2]), "=r"(d[3]) : "r"(a));
}
__device__ __forceinline__ void ldmx4t(uint32_t d[4], uint32_t a) {
    asm volatile("ldmatrix.sync.aligned.m8n8.x4.trans.shared.b16 {%0,%1,%2,%3}, [%4];"
        : "=r"(d[0]), "=r"(d[1]), "=r"(d[2]), "=r"(d[3]) : "r"(a));
}

#define CP16(dst, src) asm volatile("cp.async.cg.shared.global [%0], [%1], 16;" :: "r"(dst), "l"(src) : "memory")
#define CP_COMMIT()    asm volatile("cp.async.commit_group;" ::: "memory")
#define CP_WAIT0()     asm volatile("cp.async.wait_group 0;" ::: "memory")

// ---------------------------------------------------------------------------
// Prep: positional encoding (blocks >= 64) + weight split/pack (blocks < 64)
// ---------------------------------------------------------------------------
__global__ void prep_kernel(const float* __restrict__ wq, const float* __restrict__ wk,
                            const float* __restrict__ wv, const float* __restrict__ wo) {
    int bid = blockIdx.x;
    if (bid < 64) {
        int idx = bid * 256 + threadIdx.x;      // 0..16383
        int mat = idx >> 12, rem = idx & 4095;
        int no = rem >> 8, ks = (rem >> 5) & 7, lane = rem & 31;
        int gg = lane >> 2, uu = lane & 3;
        const float* Ws[4] = {wq, wk, wv, wo};
        const float* W = Ws[mat];
        int n = 8 * no + gg, k0 = 16 * ks + 2 * uu;
        uint32_t h0, l0, h1, l1;
        split2h(W[n*DMODEL + k0],     W[n*DMODEL + k0 + 1], h0, l0);
        split2h(W[n*DMODEL + k0 + 8], W[n*DMODEL + k0 + 9], h1, l1);
        g_wph[idx] = make_uint2(h0, h1);
        g_wpl[idx] = make_uint2(l0, l1);
    } else {
        int idx = (bid - 64) * 256 + threadIdx.x;
        if (idx >= SLEN * (DMODEL/2)) return;
        int s = idx / (DMODEL/2);
        int i = idx % (DMODEL/2);
        float e = (2.0f * (float)i) / (float)DMODEL;
        double divd = exp2((double)e * 13.287712379549449);  // 10000^e
        float fdiv = (float)divd;
        float a = (float)s / fdiv;      // fp32 angle like jax
        float sv, cv;
        sincosf(a, &sv, &cv);           // 2-ulp accurate incl. range reduction
        g_pe[s*DMODEL + 2*i]     = sv;
        g_pe[s*DMODEL + 2*i + 1] = cv;
    }
}

// ---------------------------------------------------------------------------
// QKV projection via HMMA (fp16, 3-term). blockIdx.y selects the matrix.
// Outputs: q scaled by log2e/sqrt(32) hi/lo, k hi/lo, v hi only.
// ---------------------------------------------------------------------------
__global__ __launch_bounds__(128) void qkv_mma_kernel(
        const int* __restrict__ seq, const float* __restrict__ emb) {
    int tid = threadIdx.x;
    int w = tid >> 5, lane = tid & 31;
    int g = lane >> 2, u = lane & 3;
    int m0 = (blockIdx.x >> 1) * 64 + 16 * w;
    int jbase = (blockIdx.x & 1) * 8;
    int mat = blockIdx.y;

    int ra = m0 + g, rb = ra + 8;
    int tok_a = seq[ra], tok_b = seq[rb];
    int sa = ra & (SLEN - 1), sb = rb & (SLEN - 1);
    const float* Ea = emb + (long)tok_a * DMODEL;
    const float* Eb = emb + (long)tok_b * DMODEL;
    const float* Pa = g_pe + sa * DMODEL;
    const float* Pb = g_pe + sb * DMODEL;

    uint32_t xh[8][4], xl[8][4];
    #pragma unroll
    for (int ks = 0; ks < 8; ks++) {
        int c = 16 * ks + 2 * u;
        float2 e0, p0;
        e0 = *(const float2*)(Ea + c);     p0 = *(const float2*)(Pa + c);
        split2h(e0.x + p0.x, e0.y + p0.y, xh[ks][0], xl[ks][0]);
        e0 = *(const float2*)(Eb + c);     p0 = *(const float2*)(Pb + c);
        split2h(e0.x + p0.x, e0.y + p0.y, xh[ks][1], xl[ks][1]);
        e0 = *(const float2*)(Ea + c + 8); p0 = *(const float2*)(Pa + c + 8);
        split2h(e0.x + p0.x, e0.y + p0.y, xh[ks][2], xl[ks][2]);
        e0 = *(const float2*)(Eb + c + 8); p0 = *(const float2*)(Pb + c + 8);
        split2h(e0.x + p0.x, e0.y + p0.y, xh[ks][3], xl[ks][3]);
    }

    // 1/sqrt(32) * log2(e): folds softmax's exp->exp2 conversion into Q
    const float qscale = 0.17677669529663687f * 1.4426950408889634f;

    const uint2* wph = g_wph + mat * 4096;
    const uint2* wpl = g_wpl + mat * 4096;

    float acc[8][4];
    #pragma unroll
    for (int j = 0; j < 8; j++)
        #pragma unroll
        for (int e = 0; e < 4; e++) acc[j][e] = 0.f;

    #pragma unroll
    for (int ks = 0; ks < 8; ks++) {
        #pragma unroll
        for (int j = 0; j < 8; j++) {
            int no = jbase + j;
            uint2 bhv = wph[(no * 8 + ks) * 32 + lane];
            uint2 blv = wpl[(no * 8 + ks) * 32 + lane];
            uint32_t bh[2] = { bhv.x, bhv.y };
            uint32_t bl[2] = { blv.x, blv.y };
            mma_f16(acc[j], xh[ks], bh);
            mma_f16(acc[j], xl[ks], bh);
            mma_f16(acc[j], xh[ks], bl);
        }
    }

    #pragma unroll
    for (int j = 0; j < 8; j++) {
        int cbase = (jbase + j) * 8 + 2 * u;
        if (mat == 0) {
            uint32_t h0, l0;
            split2h(acc[j][0] * qscale, acc[j][1] * qscale, h0, l0);
            *(uint32_t*)(g_qh + (long)ra * DMODEL + cbase) = h0;
            *(uint32_t*)(g_ql + (long)ra * DMODEL + cbase) = l0;
            split2h(acc[j][2] * qscale, acc[j][3] * qscale, h0, l0);
            *(uint32_t*)(g_qh + (long)rb * DMODEL + cbase) = h0;
            *(uint32_t*)(g_ql + (long)rb * DMODEL + cbase) = l0;
        } else if (mat == 1) {
            uint32_t h0, l0;
            split2h(acc[j][0], acc[j][1], h0, l0);
            *(uint32_t*)(g_kh + (long)ra * DMODEL + cbase) = h0;
            *(uint32_t*)(g_kl + (long)ra * DMODEL + cbase) = l0;
            split2h(acc[j][2], acc[j][3], h0, l0);
            *(uint32_t*)(g_kh + (long)rb * DMODEL + cbase) = h0;
            *(uint32_t*)(g_kl + (long)rb * DMODEL + cbase) = l0;
        } else {
            *(uint32_t*)(g_vh + (long)ra * DMODEL + cbase) = pack2h(acc[j][0], acc[j][1]);
            *(uint32_t*)(g_vh + (long)rb * DMODEL + cbase) = pack2h(acc[j][2], acc[j][3]);
        }
    }
}

// ---------------------------------------------------------------------------
// HMMA flash attention v6: fp16, 3-term S / 1-term PV (P-hi x V-hi),
// exponent-shifted MUFU exp2, diag/non-diag specialized softmax,
// balanced pairing + cp.async double buffering + ldmatrix.x4.
// SMEM per stage: KH,KL,VH each [128 keys][80B stride] = 30KB; 2 stages.
// ---------------------------------------------------------------------------
#define KHOFF 0
#define KLOFF 10240
#define VHOFF 20480
#define STAGE 30720
#define PSHIFT 5.0f

__device__ __forceinline__ void stage_tile(uint32_t sb,
        const char* kh, const char* kl, const char* vh, int jt, int tid) {
    long base = (long)jt * 128 * 64;   // 128 keys x 64 bytes
    #pragma unroll
    for (int it = 0; it < 2; it++) {
        int gi = tid + it * 256;
        int key = gi >> 2, q4 = gi & 3;
        int d = key * 80 + 16 * q4;
        long s = base + key * 64 + 16 * q4;
        CP16(sb + KHOFF + d, kh + s);
        CP16(sb + KLOFF + d, kl + s);
        CP16(sb + VHOFF + d, vh + s);
    }
}

__global__ __launch_bounds__(256, 2) void attn_mma_kernel() {
    extern __shared__ char smem[];
    uint32_t sbase = smem_u32(smem);
    int tid = threadIdx.x;
    int w = tid >> 5, lane = tid & 31;
    int g = lane >> 2, u = lane & 3;

    int x = blockIdx.x;
    int pu = x >> 1, side = x & 1;
    int hb = blockIdx.y;
    long hoff = (long)hb * SLEN * HDIM;

    const char* Kh = (const char*)(g_kh + hoff);
    const char* Kl = (const char*)(g_kl + hoff);
    const char* Vh = (const char*)(g_vh + hoff);
    const __half* Qbh = g_qh + hoff;
    const __half* Qbl = g_ql + hoff;
    float* PO = g_po + ((long)side * NHB + hb) * SLEN * HDIM;
    float* PL = g_pl + ((long)side * NHB + hb) * SLEN;

    int qts[2], j0s[2], j1s[2], nseg;
    if (side == 0) {
        qts[0] = pu;      j0s[0] = 0;       j1s[0] = pu + 1;
        qts[1] = 31 - pu; j0s[1] = 0;       j1s[1] = 16 - pu;
        nseg = 2;
    } else {
        qts[0] = 31 - pu; j0s[0] = 16 - pu; j1s[0] = 32 - pu;
        nseg = 1;
    }

    for (int sg = 0; sg < nseg; sg++) {
        int qt = qts[sg], j0 = j0s[sg], j1 = j1s[sg];
        __syncthreads();   // previous segment done with both buffers
        stage_tile(sbase, Kh, Kl, Vh, j0, tid);
        CP_COMMIT();

        // ---- Q A-fragments (pre-scaled by log2e/sqrt(32), pre-split) ----
        int r0 = qt * 128 + 16 * w + g;
        uint32_t qh[2][4], ql[2][4];
        #pragma unroll
        for (int kt = 0; kt < 2; kt++) {
            int c = 16 * kt + 2 * u;
            qh[kt][0] = *(const uint32_t*)(Qbh + (long)r0 * HDIM + c);
            qh[kt][1] = *(const uint32_t*)(Qbh + (long)(r0 + 8) * HDIM + c);
            qh[kt][2] = *(const uint32_t*)(Qbh + (long)r0 * HDIM + c + 8);
            qh[kt][3] = *(const uint32_t*)(Qbh + (long)(r0 + 8) * HDIM + c + 8);
            ql[kt][0] = *(const uint32_t*)(Qbl + (long)r0 * HDIM + c);
            ql[kt][1] = *(const uint32_t*)(Qbl + (long)(r0 + 8) * HDIM + c);
            ql[kt][2] = *(const uint32_t*)(Qbl + (long)r0 * HDIM + c + 8);
            ql[kt][3] = *(const uint32_t*)(Qbl + (long)(r0 + 8) * HDIM + c + 8);
        }

        float O[4][4];
        #pragma unroll
        for (int jo = 0; jo < 4; jo++)
            #pragma unroll
            for (int e = 0; e < 4; e++) O[jo][e] = 0.f;
        float lsum0 = 0.f, lsum1 = 0.f;

        for (int jt = j0; jt < j1; jt++) {
            CP_WAIT0();
            __syncthreads();
            uint32_t sb = sbase + ((jt - j0) & 1) * STAGE;
            if (jt + 1 < j1) {
                stage_tile(sbase + ((jt + 1 - j0) & 1) * STAGE, Kh, Kl, Vh, jt + 1, tid);
                CP_COMMIT();
            }

            bool diag = (jt == qt);
            int rloc0 = 16 * w + g;

            #pragma unroll
            for (int h = 0; h < 2; h++) {
                if (diag && h == 1 && w < 4) continue;   // fully masked half

                // ---- S = Q K^T over 64 keys (ldmatrix.x4 K frags) ----
                float s[8][4];
                #pragma unroll
                for (int j = 0; j < 8; j++) {
                    uint32_t ka = sb + (64*h + 8*j + (lane & 7)) * 80 + 16 * (lane >> 3);
                    uint32_t bh4[4], bl4[4];
                    ldmx4(bh4, ka + KHOFF);
                    ldmx4(bl4, ka + KLOFF);
                    s[j][0] = 0.f; s[j][1] = 0.f; s[j][2] = 0.f; s[j][3] = 0.f;
                    mma_f16(s[j], qh[0], &bh4[0]);
                    mma_f16(s[j], qh[1], &bh4[2]);
                    mma_f16(s[j], qh[0], &bl4[0]);
                    mma_f16(s[j], qh[1], &bl4[2]);
                    mma_f16(s[j], ql[0], &bh4[0]);
                    mma_f16(s[j], ql[1], &bh4[2]);
                }

                // ---- softmax: p' = 2^(|s'| - PSHIFT); shift cancels in O/L --
                if (diag) {
                    #pragma unroll
                    for (int j = 0; j < 8; j++) {
                        #pragma unroll
                        for (int e = 0; e < 4; e++) {
                            float p = ex2(fabsf(s[j][e]) - PSHIFT);
                            int col = 64*h + 8*j + 2*u + (e & 1);
                            int row = rloc0 + ((e >= 2) ? 8 : 0);
                            if (col > row) p = 0.f;
                            s[j][e] = p;
                        }
                        lsum0 += s[j][0] + s[j][1];
                        lsum1 += s[j][2] + s[j][3];
                    }
                } else {
                    #pragma unroll
                    for (int j = 0; j < 8; j++) {
                        #pragma unroll
                        for (int e = 0; e < 4; e++)
                            s[j][e] = ex2(fabsf(s[j][e]) - PSHIFT);
                        lsum0 += s[j][0] + s[j][1];
                        lsum1 += s[j][2] + s[j][3];
                    }
                }

                // ---- O += P V (P-hi only x V-hi; ldmatrix.x4.trans) ----
                #pragma unroll
                for (int kt = 0; kt < 4; kt++) {
                    uint32_t ah[4];
                    ah[0] = pack2h(s[2*kt][0],   s[2*kt][1]);
                    ah[1] = pack2h(s[2*kt][2],   s[2*kt][3]);
                    ah[2] = pack2h(s[2*kt+1][0], s[2*kt+1][1]);
                    ah[3] = pack2h(s[2*kt+1][2], s[2*kt+1][3]);
                    uint32_t rowb = sb + (64*h + 16*kt + (lane & 15)) * 80 + 16 * (lane >> 4);
                    #pragma unroll
                    for (int jop = 0; jop < 2; jop++) {
                        uint32_t vh4[4];
                        ldmx4t(vh4, rowb + VHOFF + 32 * jop);
                        mma_f16(O[2*jop],   ah, &vh4[0]);
                        mma_f16(O[2*jop+1], ah, &vh4[2]);
                    }
                }
            }
        }

        // ---- store unnormalized partial O + partial row sums ----
        #pragma unroll
        for (int jo = 0; jo < 4; jo++) {
            int cb = 8 * jo + 2 * u;
            *(float2*)(PO + (long)r0 * HDIM + cb)       = make_float2(O[jo][0], O[jo][1]);
            *(float2*)(PO + (long)(r0 + 8) * HDIM + cb) = make_float2(O[jo][2], O[jo][3]);
        }
        lsum0 += __shfl_xor_sync(0xffffffffu, lsum0, 1);
        lsum0 += __shfl_xor_sync(0xffffffffu, lsum0, 2);
        lsum1 += __shfl_xor_sync(0xffffffffu, lsum1, 1);
        lsum1 += __shfl_xor_sync(0xffffffffu, lsum1, 2);
        if (u == 0) {
            PL[r0]     = lsum0;
            PL[r0 + 8] = lsum1;
        }
    }
}

// ---------------------------------------------------------------------------
// Output projection with fused attention epilogue (n split into quarters).
// Plain-view mapping: X row ra (within-batch row sa) belongs ENTIRELY to head
// h' = sa>>10; column c is seq position (sa&1023)*4 + (c>>5), dim c&31.
// For kstep ks: pos offset p = ks>>1, dim base = (ks&1)*16 + 2u (+8).
// ---------------------------------------------------------------------------
__global__ __launch_bounds__(128) void oproj_mma_kernel(float* __restrict__ out) {
    int tid = threadIdx.x;
    int w = tid >> 5, lane = tid & 31;
    int g = lane >> 2, u = lane & 3;
    int m0 = (blockIdx.x >> 2) * 64 + 16 * w;
    int jbase = (blockIdx.x & 3) * 4;

    int ra = m0 + g, rb = ra + 8;
    int ba = ra >> 12, sa = ra & (SLEN - 1);
    int bb = rb >> 12, sb = rb & (SLEN - 1);
    int ha = sa >> 10, hb2 = sb >> 10;                 // head index (fixed per row)
    int pa0 = (sa & 1023) * 4, pb0 = (sb & 1023) * 4;  // base seq position
    bool two_a = (sa & 1023) >= 512;
    bool two_b = (sb & 1023) >= 512;
    const float* PO1 = g_po + (long)NHB * SLEN * HDIM;
    const float* PL1 = g_pl + NHB * SLEN;

    // normalizers: one per pos offset (0..3)
    float inva[4], invb[4];
    #pragma unroll
    for (int p = 0; p < 4; p++) {
        long ia = ((long)(ba * 4 + ha)) * SLEN + pa0 + p;
        float la = g_pl[ia] + (two_a ? PL1[ia] : 0.f);
        inva[p] = 1.0f / la;
        long ib = ((long)(bb * 4 + hb2)) * SLEN + pb0 + p;
        float lb = g_pl[ib] + (two_b ? PL1[ib] : 0.f);
        invb[p] = 1.0f / lb;
    }

    uint32_t xh[8][4], xl[8][4];
    #pragma unroll
    for (int ks = 0; ks < 8; ks++) {
        int p = ks >> 1;
        int d0 = (ks & 1) * 16 + 2 * u;
        long base_a = (((long)(ba * 4 + ha)) * SLEN + pa0 + p) * HDIM;
        float2 a0 = *(const float2*)(g_po + base_a + d0);
        float2 a1 = *(const float2*)(g_po + base_a + d0 + 8);
        if (two_a) {
            float2 q0 = *(const float2*)(PO1 + base_a + d0);
            float2 q1 = *(const float2*)(PO1 + base_a + d0 + 8);
            a0.x += q0.x; a0.y += q0.y; a1.x += q1.x; a1.y += q1.y;
        }
        split2h(a0.x * inva[p], a0.y * inva[p], xh[ks][0], xl[ks][0]);
        split2h(a1.x * inva[p], a1.y * inva[p], xh[ks][2], xl[ks][2]);

        long base_b = (((long)(bb * 4 + hb2)) * SLEN + pb0 + p) * HDIM;
        float2 b0 = *(const float2*)(g_po + base_b + d0);
        float2 b1 = *(const float2*)(g_po + base_b + d0 + 8);
        if (two_b) {
            float2 q0 = *(const float2*)(PO1 + base_b + d0);
            float2 q1 = *(const float2*)(PO1 + base_b + d0 + 8);
            b0.x += q0.x; b0.y += q0.y; b1.x += q1.x; b1.y += q1.y;
        }
        split2h(b0.x * invb[p], b0.y * invb[p], xh[ks][1], xl[ks][1]);
        split2h(b1.x * invb[p], b1.y * invb[p], xh[ks][3], xl[ks][3]);
    }

    const uint2* wph = g_wph + 3 * 4096;
    const uint2* wpl = g_wpl + 3 * 4096;

    float acc[4][4];
    #pragma unroll
    for (int j = 0; j < 4; j++)
        #pragma unroll
        for (int e = 0; e < 4; e++) acc[j][e] = 0.f;

    #pragma unroll
    for (int ks = 0; ks < 8; ks++) {
        #pragma unroll
        for (int j = 0; j < 4; j++) {
            int no = jbase + j;
            uint2 bhv = wph[(no * 8 + ks) * 32 + lane];
            uint2 blv = wpl[(no * 8 + ks) * 32 + lane];
            uint32_t bh[2] = { bhv.x, bhv.y };
            uint32_t bl[2] = { blv.x, blv.y };
            mma_f16(acc[j], xh[ks], bh);
            mma_f16(acc[j], xl[ks], bh);
            mma_f16(acc[j], xh[ks], bl);
        }
    }

    #pragma unroll
    for (int j = 0; j < 4; j++) {
        int cbase = (jbase + j) * 8 + 2 * u;
        *(float2*)(out + (long)ra * DMODEL + cbase) = make_float2(acc[j][0], acc[j][1]);
        *(float2*)(out + (long)rb * DMODEL + cbase) = make_float2(acc[j][2], acc[j][3]);
    }
}

extern "C" void kernel_launch(void* const* d_in, const int* in_sizes, int n_in,
                              void* d_out, int out_size) {
    const int*   seq = (const int*)d_in[0];
    const float* emb = (const float*)d_in[1];
    const float* wq  = (const float*)d_in[2];
    const float* wk  = (const float*)d_in[3];
    const float* wv  = (const float*)d_in[4];
    const float* wo  = (const float*)d_in[5];
    float* out = (float*)d_out;

    cudaFuncSetAttribute(attn_mma_kernel,
                         cudaFuncAttributeMaxDynamicSharedMemorySize, 2 * STAGE);

    prep_kernel<<<64 + (SLEN*(DMODEL/2) + 255)/256, 256>>>(wq, wk, wv, wo);
    qkv_mma_kernel<<<dim3(256, 3), 128>>>(seq, emb);
    attn_mma_kernel<<<dim3(32, NHB), 256, 2 * STAGE>>>();
    oproj_mma_kernel<<<512, 128>>>(out);
}